// round 6
// baseline (speedup 1.0000x reference)
#include <cuda_runtime.h>
#include <math.h>

#define NTH 1024
#define RPB 8

typedef unsigned long long ull;

// ---------------- transposed weight scratch (device globals, no allocs) ----
__device__ float g_WhhT[256*768];    // [i*768+o]
__device__ float g_WihT[8*768];      // [ii*768+o]
__device__ float g_e1T [256*256];    // [i*256+o]
__device__ float g_e2T [256*512];    // [i*512+oo]
__device__ float g_oWT [4][256*256]; // [l][i*256+o]

__global__ void prep_kernel(const float* __restrict__ Wih, const float* __restrict__ Whh,
                            const float* __restrict__ eW1, const float* __restrict__ eW2,
                            const float* __restrict__ oW1, const float* __restrict__ oW2,
                            const float* __restrict__ oW3, const float* __restrict__ oW4)
{
    for (int idx = blockIdx.x*blockDim.x + threadIdx.x; idx < 196608;
         idx += gridDim.x*blockDim.x) {
        { int o = idx/256, i = idx%256; g_WhhT[i*768+o] = Whh[idx]; }
        if (idx < 6144)  { int o = idx/8,  ii = idx%8;  g_WihT[ii*768+o] = Wih[idx]; }
        if (idx < 65536) {
            int o = idx/256, i = idx%256;
            g_e1T[i*256+o]    = eW1[idx];
            g_oWT[0][i*256+o] = oW1[idx];
            g_oWT[1][i*256+o] = oW2[idx];
            g_oWT[2][i*256+o] = oW3[idx];
            g_oWT[3][i*256+o] = oW4[idx];
        }
        if (idx < 131072){ int oo = idx/256, i = idx%256; g_e2T[i*512+oo] = eW2[idx]; }
    }
}

// ---------------- f32x2 helpers ----------------
__device__ __forceinline__ ull pack2(float a, float b){
    ull r; asm("mov.b64 %0, {%1, %2};" : "=l"(r) : "f"(a), "f"(b)); return r;
}
__device__ __forceinline__ void unpack2(ull v, float& a, float& b){
    asm("mov.b64 {%0, %1}, %2;" : "=f"(a), "=f"(b) : "l"(v));
}
__device__ __forceinline__ void fma2(ull& acc, ull a, ull b){
    asm("fma.rn.f32x2 %0, %1, %2, %0;" : "+l"(acc) : "l"(a), "l"(b));
}

__device__ __forceinline__ float selu_f(float x){
    const float sc = 1.0507009873554805f, al = 1.6732632423543772f;
    return x > 0.f ? sc*x : sc*(al*expm1f(x));
}
__device__ __forceinline__ float sigmoid_f(float x){ return 1.f/(1.f+expf(-x)); }

// Activation layout: elem (row r, col c) at buf[(r>>2)*1024 + c*4 + (r&3)], 2048 floats.
// Split-K matvec: thread (o, q) accumulates all 8 rows over i in [q*64, q*64+64).
// Partials -> Pp[q*2048 + ...]; combine phase: 2 elems per thread, adds bias + activation.
template<int ACT>
__device__ __forceinline__ void smatvec(const float* __restrict__ WT,
                                        const float* __restrict__ bias,
                                        const float* __restrict__ inT,
                                        float* __restrict__ outT,
                                        float* __restrict__ Pp,
                                        int o, int q, int tid)
{
    const float4* in4 = (const float4*)inT;
    const float* wp = WT + o + (q*64)*256;
    const int i0 = q*64;
    ull a0 = 0ull, a1 = 0ull, a2 = 0ull, a3 = 0ull;
#pragma unroll 8
    for (int ii = 0; ii < 64; ii++) {
        float w = __ldg(wp + ii*256);
        ull w2 = pack2(w, w);
        float4 u = in4[i0 + ii];
        float4 v = in4[256 + i0 + ii];
        fma2(a0, pack2(u.x,u.y), w2); fma2(a1, pack2(u.z,u.w), w2);
        fma2(a2, pack2(v.x,v.y), w2); fma2(a3, pack2(v.z,v.w), w2);
    }
    float f0,f1,f2,f3,f4,f5,f6,f7;
    unpack2(a0,f0,f1); unpack2(a1,f2,f3); unpack2(a2,f4,f5); unpack2(a3,f6,f7);
    float* Pq = Pp + q*2048;
    *(float4*)(Pq + o*4)        = make_float4(f0,f1,f2,f3);
    *(float4*)(Pq + 1024 + o*4) = make_float4(f4,f5,f6,f7);
    __syncthreads();
    const int e = tid*2;
    float2 s0 = *(float2*)(Pp + e);
    float2 s1 = *(float2*)(Pp + 2048 + e);
    float2 s2 = *(float2*)(Pp + 4096 + e);
    float2 s3 = *(float2*)(Pp + 6144 + e);
    float b = bias[(e & 1023) >> 2];
    float vx = s0.x + s1.x + s2.x + s3.x + b;
    float vy = s0.y + s1.y + s2.y + s3.y + b;
    if (ACT == 1) { vx = selu_f(vx); vy = selu_f(vy); }
    else if (ACT == 2) { vx = fmaxf(vx, 0.f); vy = fmaxf(vy, 0.f); }
    *(float2*)(outT + e) = make_float2(vx, vy);
    __syncthreads();
}

__device__ __forceinline__ void feval(const float* __restrict__ inT, float* __restrict__ outT,
                                      float* __restrict__ aT, float* __restrict__ bT,
                                      float* __restrict__ Pp,
                                      const float* ob1, const float* ob2,
                                      const float* ob3, const float* ob4,
                                      int o, int q, int tid)
{
    smatvec<1>(g_oWT[0], ob1, inT, aT, Pp, o, q, tid);
    smatvec<1>(g_oWT[1], ob2, aT,  bT, Pp, o, q, tid);
    smatvec<1>(g_oWT[2], ob3, bT,  aT, Pp, o, q, tid);
    smatvec<0>(g_oWT[3], ob4, aT, outT, Pp, o, q, tid);
}

// ---------------- main persistent kernel ----------------
__global__ __launch_bounds__(NTH, 1)
void node_kernel(const float* __restrict__ x,     const float* __restrict__ meta,
                 const float* __restrict__ eps,   const float* __restrict__ times,
                 const float* __restrict__ doses,
                 const float* __restrict__ gbih,  const float* __restrict__ gbhh,
                 const float* __restrict__ eb1,   const float* __restrict__ eb2,
                 const float* __restrict__ ob1,   const float* __restrict__ ob2,
                 const float* __restrict__ ob3,   const float* __restrict__ ob4,
                 const float* __restrict__ fcW,   const float* __restrict__ fcb,
                 float* __restrict__ out)
{
    extern __shared__ float sm[];
    float* yT   = sm + 0*2048;
    float* tmpT = sm + 1*2048;   // stage input / k7
    float* aT   = sm + 2*2048;   // scratch; reused as reduction buffer
    float* bT   = sm + 3*2048;
    float* y5T  = sm + 4*2048;
    float* k1T  = sm + 5*2048;   // reused as x cache during GRU
    float* k2T  = sm + 6*2048;
    float* k3T  = sm + 7*2048;
    float* k4T  = sm + 8*2048;
    float* k5T  = sm + 9*2048;
    float* k6T  = sm +10*2048;
    float* Pp   = sm +11*2048;   // 4*2048 split-K partials; gate arrays during GRU
    float* red  = aT;
    float* xc   = k1T;

    __shared__ float t_s[8], t1_s[8], dt_s[8], d_s[8], ds_s[8], meta_s[32];
    __shared__ int   act_s[8], accfl[8];

    const int tid  = threadIdx.x;
    const int o    = tid & 255;
    const int q    = tid >> 8;       // 0..3
    const int wid  = tid >> 5;
    const int lane = tid & 31;
    const int r0   = blockIdx.x * RPB;
    const int e2i  = tid*2;          // my 2 elems in [0,2048)

    // ---- caches ----
    for (int e = tid; e < 2048; e += NTH) { xc[e] = x[r0*256 + e]; yT[e] = 0.f; }
    if (tid < 32) meta_s[tid] = meta[r0*4 + tid];

    // GRU: gate-split. q in {0,1,2} -> gate q; q==3 idles in accumulation.
    const int g = (q < 3) ? q : 2;
    float wg[8], wn[8];
#pragma unroll
    for (int ii = 0; ii < 8; ii++) {
        wg[ii] = g_WihT[ii*768 + o + g*256];
        wn[ii] = g_WihT[ii*768 + o + 512];
    }
    // accumulator init: gates r,z get combined biases; gate n gets hidden bias only
    const float binit = (g < 2) ? (gbih[o + g*256] + gbhh[o + g*256]) : gbhh[o + 512];
    const float bin_  = gbih[o + 512];
    const float* wgp  = g_WhhT + o + g*256;
    __syncthreads();

    // ---------------- Phase A: GRU over 64 timesteps ----------------
    for (int t = 0; t < 64; t++) {
        ull a0 = pack2(binit,binit), a1 = a0, a2 = a0, a3 = a0;
        const float4* h4 = (const float4*)yT;
#pragma unroll 4
        for (int i = 0; i < 256; i++) {
            float w = __ldg(wgp + i*768);
            ull w2 = pack2(w, w);
            float4 u = h4[i];
            float4 v = h4[256 + i];
            fma2(a0, pack2(u.x,u.y), w2); fma2(a1, pack2(u.z,u.w), w2);
            fma2(a2, pack2(v.x,v.y), w2); fma2(a3, pack2(v.z,v.w), w2);
        }
        float f[8];
        unpack2(a0,f[0],f[1]); unpack2(a1,f[2],f[3]);
        unpack2(a2,f[4],f[5]); unpack2(a3,f[6],f[7]);
        if (g < 2) {   // fold input projection for gates r,z (q==3 harmless dup of q... skip)
#pragma unroll
            for (int r = 0; r < 8; r++) {
                float s = 0.f;
#pragma unroll
                for (int c = 0; c < 4; c++) s = fmaf(xc[r*256 + t*4 + c], wg[c], s);
#pragma unroll
                for (int c = 0; c < 4; c++) s = fmaf(meta_s[r*4 + c], wg[4+c], s);
                f[r] += s;
            }
        }
        if (q < 3) {
            float* Gq = Pp + q*2048;
            *(float4*)(Gq + o*4)        = make_float4(f[0],f[1],f[2],f[3]);
            *(float4*)(Gq + 1024 + o*4) = make_float4(f[4],f[5],f[6],f[7]);
        }
        __syncthreads();
        if (q < 2) {   // nonlinearity: rows 4q..4q+3, col o
            const int bse = q*1024 + o*4;
            float4 AR = *(float4*)(Pp + bse);
            float4 AZ = *(float4*)(Pp + 2048 + bse);
            float4 HN = *(float4*)(Pp + 4096 + bse);
            float arr[4] = {AR.x,AR.y,AR.z,AR.w};
            float azr[4] = {AZ.x,AZ.y,AZ.z,AZ.w};
            float hnr[4] = {HN.x,HN.y,HN.z,HN.w};
            float hnew[4];
#pragma unroll
            for (int k = 0; k < 4; k++) {
                int r = 4*q + k;
                float inn = bin_;
#pragma unroll
                for (int c = 0; c < 4; c++) inn = fmaf(xc[r*256 + t*4 + c], wn[c], inn);
#pragma unroll
                for (int c = 0; c < 4; c++) inn = fmaf(meta_s[r*4 + c], wn[4+c], inn);
                float rg = sigmoid_f(arr[k]);
                float zg = sigmoid_f(azr[k]);
                float nn = tanhf(inn + rg*hnr[k]);
                float ho = yT[bse + k];
                hnew[k] = (1.f - zg)*nn + zg*ho;
            }
            *(float4*)(yT + bse) = make_float4(hnew[0],hnew[1],hnew[2],hnew[3]);
        }
        __syncthreads();
    }

    // ---------------- Phase B: encoder -> y0 ----------------
    smatvec<2>(g_e1T, eb1, yT, bT, Pp, o, q, tid);   // relu into bT
    if (q < 2) {
        float bm = eb2[o], bs = eb2[o + 256];
        ull am0 = pack2(bm,bm), am1 = pack2(bm,bm);
        ull as0 = pack2(bs,bs), as1 = pack2(bs,bs);
        const float4* a4 = (const float4*)(bT + q*1024);
        const float* wmp = g_e2T + o;
        const float* wsp = g_e2T + o + 256;
#pragma unroll 4
        for (int i = 0; i < 256; i++) {
            float wm = __ldg(wmp + i*512), ws = __ldg(wsp + i*512);
            float4 p = a4[i];
            ull p01 = pack2(p.x,p.y), p23 = pack2(p.z,p.w);
            ull wm2 = pack2(wm,wm), ws2 = pack2(ws,ws);
            fma2(am0, p01, wm2); fma2(am1, p23, wm2);
            fma2(as0, p01, ws2); fma2(as1, p23, ws2);
        }
        float mm[4], ss[4];
        unpack2(am0, mm[0], mm[1]); unpack2(am1, mm[2], mm[3]);
        unpack2(as0, ss[0], ss[1]); unpack2(as1, ss[2], ss[3]);
        float4 y0;
        y0.x = fmaf(eps[(r0 + 4*q + 0)*256 + o], ss[0], mm[0]);
        y0.y = fmaf(eps[(r0 + 4*q + 1)*256 + o], ss[1], mm[1]);
        y0.z = fmaf(eps[(r0 + 4*q + 2)*256 + o], ss[2], mm[2]);
        y0.w = fmaf(eps[(r0 + 4*q + 3)*256 + o], ss[3], mm[3]);
        *(float4*)(yT + q*1024 + o*4) = y0;
    }
    __syncthreads();

    // ---------------- Phase C: 4 x dopri5 ----------------
    const float A21 = 0.2f;
    const float A31 = (float)(3.0/40.0),  A32 = (float)(9.0/40.0);
    const float A41 = (float)(44.0/45.0), A42 = (float)(-56.0/15.0), A43 = (float)(32.0/9.0);
    const float A51 = (float)(19372.0/6561.0), A52 = (float)(-25360.0/2187.0),
                A53 = (float)(64448.0/6561.0), A54 = (float)(-212.0/729.0);
    const float A61 = (float)(9017.0/3168.0), A62 = (float)(-355.0/33.0),
                A63 = (float)(46732.0/5247.0), A64 = (float)(49.0/176.0),
                A65 = (float)(-5103.0/18656.0);
    const float BC0 = (float)(35.0/384.0), BC2 = (float)(500.0/1113.0),
                BC3 = (float)(125.0/192.0), BC4 = (float)(-2187.0/6784.0),
                BC5 = (float)(11.0/84.0);
    const float EC0 = (float)(35.0/384.0 - 5179.0/57600.0);
    const float EC2 = (float)(500.0/1113.0 - 7571.0/16695.0);
    const float EC3 = (float)(125.0/192.0 - 393.0/640.0);
    const float EC4 = (float)(-2187.0/6784.0 + 92097.0/339200.0);
    const float EC5 = (float)(11.0/84.0 - 187.0/2100.0);
    const float EC6 = (float)(-1.0/40.0);

    // my 2 elems map to rows re0, re0+1
    const int re0 = ((e2i >> 10) << 2) | (e2i & 3);

    for (int j = 0; j < 4; j++) {
        if (tid < 8) {
            int row = r0 + tid;
            float t0v = times[(j*1024 + row)*2 + 0];
            float t1v = times[(j*1024 + row)*2 + 1];
            t_s[tid]  = t0v;
            t1_s[tid] = t1v;
            dt_s[tid] = fmaxf(t1v - t0v, 1e-6f) * 0.1f;
            ds_s[tid] = (t0v < t1v) ? doses[j*1024 + row] : 0.f;
        }
        __syncthreads();
        {
            float2 y = *(float2*)(yT + e2i);
            y.x += ds_s[re0]; y.y += ds_s[re0 + 1];
            *(float2*)(yT + e2i) = y;
        }

        for (int step = 0; step < 32; step++) {
            int myact = 0;
            if (tid < 8) {
                float tt = t_s[tid], t1v = t1_s[tid];
                myact = (tt < t1v) ? 1 : 0;
                act_s[tid] = myact;
                float rem = fmaxf(t1v - tt, 0.f);
                d_s[tid] = fminf(fmaxf(dt_s[tid], 0.f), rem);
            }
            if (!__syncthreads_or(myact)) break;   // uniform exit

            const float d0 = d_s[re0], d1 = d_s[re0 + 1];

#define COMB2(DST, EX, EY) do { \
            float2 _y = *(float2*)(yT + e2i); \
            float2 _t; \
            _t.x = fmaf(d0, (EX), _y.x); _t.y = fmaf(d1, (EY), _y.y); \
            *(float2*)(DST + e2i) = _t; } while(0)

            feval(yT, k1T, aT, bT, Pp, ob1, ob2, ob3, ob4, o, q, tid);
            {
                float2 a = *(float2*)(k1T + e2i);
                COMB2(tmpT, A21*a.x, A21*a.y);
            }
            __syncthreads();
            feval(tmpT, k2T, aT, bT, Pp, ob1, ob2, ob3, ob4, o, q, tid);
            {
                float2 a = *(float2*)(k1T + e2i); float2 b = *(float2*)(k2T + e2i);
                COMB2(tmpT, A31*a.x + A32*b.x, A31*a.y + A32*b.y);
            }
            __syncthreads();
            feval(tmpT, k3T, aT, bT, Pp, ob1, ob2, ob3, ob4, o, q, tid);
            {
                float2 a = *(float2*)(k1T + e2i); float2 b = *(float2*)(k2T + e2i);
                float2 c = *(float2*)(k3T + e2i);
                COMB2(tmpT, A41*a.x + A42*b.x + A43*c.x,
                            A41*a.y + A42*b.y + A43*c.y);
            }
            __syncthreads();
            feval(tmpT, k4T, aT, bT, Pp, ob1, ob2, ob3, ob4, o, q, tid);
            {
                float2 a = *(float2*)(k1T + e2i); float2 b = *(float2*)(k2T + e2i);
                float2 c = *(float2*)(k3T + e2i); float2 e = *(float2*)(k4T + e2i);
                COMB2(tmpT, A51*a.x + A52*b.x + A53*c.x + A54*e.x,
                            A51*a.y + A52*b.y + A53*c.y + A54*e.y);
            }
            __syncthreads();
            feval(tmpT, k5T, aT, bT, Pp, ob1, ob2, ob3, ob4, o, q, tid);
            {
                float2 a = *(float2*)(k1T + e2i); float2 b = *(float2*)(k2T + e2i);
                float2 c = *(float2*)(k3T + e2i); float2 e = *(float2*)(k4T + e2i);
                float2 f = *(float2*)(k5T + e2i);
                COMB2(tmpT, A61*a.x + A62*b.x + A63*c.x + A64*e.x + A65*f.x,
                            A61*a.y + A62*b.y + A63*c.y + A64*e.y + A65*f.y);
            }
            __syncthreads();
            feval(tmpT, k6T, aT, bT, Pp, ob1, ob2, ob3, ob4, o, q, tid);
            {
                float2 a = *(float2*)(k1T + e2i); float2 c = *(float2*)(k3T + e2i);
                float2 e = *(float2*)(k4T + e2i); float2 f = *(float2*)(k5T + e2i);
                float2 g6 = *(float2*)(k6T + e2i);
                COMB2(y5T, BC0*a.x + BC2*c.x + BC3*e.x + BC4*f.x + BC5*g6.x,
                           BC0*a.y + BC2*c.y + BC3*e.y + BC4*f.y + BC5*g6.y);
            }
            __syncthreads();
            feval(y5T, tmpT, aT, bT, Pp, ob1, ob2, ob3, ob4, o, q, tid);   // k7 -> tmpT

            // error-norm contributions -> red (== aT, free now)
            {
                float2 a = *(float2*)(k1T + e2i); float2 c = *(float2*)(k3T + e2i);
                float2 e = *(float2*)(k4T + e2i); float2 f = *(float2*)(k5T + e2i);
                float2 g6 = *(float2*)(k6T + e2i); float2 s7 = *(float2*)(tmpT + e2i);
                float2 y = *(float2*)(yT + e2i);  float2 y5 = *(float2*)(y5T + e2i);
                float ex = EC0*a.x + EC2*c.x + EC3*e.x + EC4*f.x + EC5*g6.x + EC6*s7.x;
                float ey = EC0*a.y + EC2*c.y + EC3*e.y + EC4*f.y + EC5*g6.y + EC6*s7.y;
                float qx = d0*ex / (1e-6f + 1e-3f*fmaxf(fabsf(y.x), fabsf(y5.x)));
                float qy = d1*ey / (1e-6f + 1e-3f*fmaxf(fabsf(y.y), fabsf(y5.y)));
                *(float2*)(red + e2i) = make_float2(qx*qx, qy*qy);
            }
            __syncthreads();
            if (wid < 8) {
                int r = wid;
                const float* rp = red + (r>>2)*1024 + (r&3);
                float s = 0.f;
#pragma unroll
                for (int c = 0; c < 8; c++) s += rp[(lane + 32*c)*4];
                s += __shfl_xor_sync(0xffffffffu, s, 16);
                s += __shfl_xor_sync(0xffffffffu, s, 8);
                s += __shfl_xor_sync(0xffffffffu, s, 4);
                s += __shfl_xor_sync(0xffffffffu, s, 2);
                s += __shfl_xor_sync(0xffffffffu, s, 1);
                if (lane == 0) {
                    float en = sqrtf(s * (1.f/256.f));
                    int active = act_s[r];
                    int acc = (en <= 1.f) && active;
                    accfl[r] = acc;
                    float dtc = d_s[r];
                    if (acc) t_s[r] += dtc;
                    if (active) {
                        float fac = 0.9f * powf(en + 1e-10f, -0.2f);
                        fac = fminf(fmaxf(fac, 0.2f), 10.f);
                        dt_s[r] = fmaxf(dtc, 1e-8f) * fac;
                    }
                }
            }
            __syncthreads();
            {
                float2 y = *(float2*)(yT + e2i);
                float2 y5 = *(float2*)(y5T + e2i);
                if (accfl[re0])     y.x = y5.x;
                if (accfl[re0 + 1]) y.y = y5.y;
                *(float2*)(yT + e2i) = y;
            }
            __syncthreads();
#undef COMB2
        }
    }

    // ---------------- Phase D: linear head ----------------
    {
        float fcw0 = fcW[(e2i & 1023) >> 2];
        float2 y = *(float2*)(yT + e2i);
        *(float2*)(red + e2i) = make_float2(y.x*fcw0, y.y*fcw0);
        __syncthreads();
        if (wid < 8) {
            int r = wid;
            const float* rp = red + (r>>2)*1024 + (r&3);
            float s = 0.f;
#pragma unroll
            for (int c = 0; c < 8; c++) s += rp[(lane + 32*c)*4];
            s += __shfl_xor_sync(0xffffffffu, s, 16);
            s += __shfl_xor_sync(0xffffffffu, s, 8);
            s += __shfl_xor_sync(0xffffffffu, s, 4);
            s += __shfl_xor_sync(0xffffffffu, s, 2);
            s += __shfl_xor_sync(0xffffffffu, s, 1);
            if (lane == 0) {
                s += fcb[0];
#pragma unroll
                for (int c = 0; c < 4; c++) s += meta_s[r*4 + c] * fcW[256 + c];
                out[r0 + r] = s;
            }
        }
    }
}

extern "C" void kernel_launch(void* const* d_in, const int* in_sizes, int n_in,
                              void* d_out, int out_size)
{
    const float* x     = (const float*)d_in[0];
    const float* meta  = (const float*)d_in[1];
    const float* eps   = (const float*)d_in[2];
    const float* times = (const float*)d_in[3];
    const float* doses = (const float*)d_in[4];
    const float* gWih  = (const float*)d_in[5];
    const float* gWhh  = (const float*)d_in[6];
    const float* gbih  = (const float*)d_in[7];
    const float* gbhh  = (const float*)d_in[8];
    const float* eW1   = (const float*)d_in[9];
    const float* eb1   = (const float*)d_in[10];
    const float* eW2   = (const float*)d_in[11];
    const float* eb2   = (const float*)d_in[12];
    const float* oW1   = (const float*)d_in[13];
    const float* ob1   = (const float*)d_in[14];
    const float* oW2   = (const float*)d_in[15];
    const float* ob2   = (const float*)d_in[16];
    const float* oW3   = (const float*)d_in[17];
    const float* ob3   = (const float*)d_in[18];
    const float* oW4   = (const float*)d_in[19];
    const float* ob4   = (const float*)d_in[20];
    const float* fcW   = (const float*)d_in[21];
    const float* fcb   = (const float*)d_in[22];
    float* out = (float*)d_out;

    prep_kernel<<<768, 256>>>(gWih, gWhh, eW1, eW2, oW1, oW2, oW3, oW4);

    const int smem_bytes = 15 * 2048 * sizeof(float);   // 122880
    static int attr_done = 0;
    if (!attr_done) {
        cudaFuncSetAttribute(node_kernel, cudaFuncAttributeMaxDynamicSharedMemorySize, smem_bytes);
        attr_done = 1;
    }
    node_kernel<<<128, NTH, smem_bytes>>>(x, meta, eps, times, doses,
                                          gbih, gbhh, eb1, eb2,
                                          ob1, ob2, ob3, ob4, fcW, fcb, out);
}

// round 7
// speedup vs baseline: 1.4833x; 1.4833x over previous
#include <cuda_runtime.h>
#include <math.h>

#define NTH 512
#define RPB 4

typedef unsigned long long ull;

// ---------------- transposed weight scratch (device globals, no allocs) ----
__device__ float g_WhhT[256*768];    // [i*768+o]
__device__ float g_WihT[8*768];      // [ii*768+o]
__device__ float g_e1T [256*256];    // [i*256+o]
__device__ float g_e2T [256*512];    // [i*512+oo]
__device__ float g_oWT [4][256*256]; // [l][i*256+o]

__global__ void prep_kernel(const float* __restrict__ Wih, const float* __restrict__ Whh,
                            const float* __restrict__ eW1, const float* __restrict__ eW2,
                            const float* __restrict__ oW1, const float* __restrict__ oW2,
                            const float* __restrict__ oW3, const float* __restrict__ oW4)
{
    for (int idx = blockIdx.x*blockDim.x + threadIdx.x; idx < 196608;
         idx += gridDim.x*blockDim.x) {
        { int o = idx/256, i = idx%256; g_WhhT[i*768+o] = Whh[idx]; }
        if (idx < 6144)  { int o = idx/8,  ii = idx%8;  g_WihT[ii*768+o] = Wih[idx]; }
        if (idx < 65536) {
            int o = idx/256, i = idx%256;
            g_e1T[i*256+o]    = eW1[idx];
            g_oWT[0][i*256+o] = oW1[idx];
            g_oWT[1][i*256+o] = oW2[idx];
            g_oWT[2][i*256+o] = oW3[idx];
            g_oWT[3][i*256+o] = oW4[idx];
        }
        if (idx < 131072){ int oo = idx/256, i = idx%256; g_e2T[i*512+oo] = eW2[idx]; }
    }
}

// ---------------- f32x2 helpers ----------------
__device__ __forceinline__ ull pack2(float a, float b){
    ull r; asm("mov.b64 %0, {%1, %2};" : "=l"(r) : "f"(a), "f"(b)); return r;
}
__device__ __forceinline__ void unpack2(ull v, float& a, float& b){
    asm("mov.b64 {%0, %1}, %2;" : "=f"(a), "=f"(b) : "l"(v));
}
__device__ __forceinline__ void fma2(ull& acc, ull a, ull b){
    asm("fma.rn.f32x2 %0, %1, %2, %0;" : "+l"(acc) : "l"(a), "l"(b));
}

__device__ __forceinline__ float selu_f(float x){
    const float sc = 1.0507009873554805f, al = 1.6732632423543772f;
    return x > 0.f ? sc*x : sc*(al*expm1f(x));
}
__device__ __forceinline__ float sigmoid_f(float x){ return 1.f/(1.f+expf(-x)); }

// Activation layout: elem (row r in [0,4), col c in [0,256)) at buf[c*4 + r]; 1024 floats.
// Split-K matvec over 8 q-chunks of 32 i's; thread (oc, q) owns cols 4oc..4oc+3, all 4 rows.
__device__ __noinline__ void smatvec(const float* __restrict__ WT,
                                     const float* __restrict__ bias,
                                     const float* __restrict__ inT,
                                     float* __restrict__ outT,
                                     float* __restrict__ Pp,
                                     int oc, int q, int tid, int act)
{
    const float4* in4 = (const float4*)inT;
    const float4* w4p = (const float4*)WT + q*32*64 + oc;
    ull a0=0,a1=0,a2=0,a3=0,a4=0,a5=0,a6=0,a7=0;
#pragma unroll
    for (int ii = 0; ii < 32; ii++) {
        float4 w = __ldg(w4p + ii*64);
        float4 u = in4[q*32 + ii];
        ull u01 = pack2(u.x,u.y), u23 = pack2(u.z,u.w);
        ull wx = pack2(w.x,w.x), wy = pack2(w.y,w.y);
        ull wz = pack2(w.z,w.z), ww = pack2(w.w,w.w);
        fma2(a0,u01,wx); fma2(a1,u23,wx);
        fma2(a2,u01,wy); fma2(a3,u23,wy);
        fma2(a4,u01,wz); fma2(a5,u23,wz);
        fma2(a6,u01,ww); fma2(a7,u23,ww);
    }
    float* P = Pp + q*1024 + oc*16;
    float f0,f1,f2,f3;
    unpack2(a0,f0,f1); unpack2(a1,f2,f3); *(float4*)(P+0)  = make_float4(f0,f1,f2,f3);
    unpack2(a2,f0,f1); unpack2(a3,f2,f3); *(float4*)(P+4)  = make_float4(f0,f1,f2,f3);
    unpack2(a4,f0,f1); unpack2(a5,f2,f3); *(float4*)(P+8)  = make_float4(f0,f1,f2,f3);
    unpack2(a6,f0,f1); unpack2(a7,f2,f3); *(float4*)(P+12) = make_float4(f0,f1,f2,f3);
    __syncthreads();
    const int e = tid*2;
    float vx = 0.f, vy = 0.f;
#pragma unroll
    for (int p = 0; p < 8; p++) {
        float2 s = *(float2*)(Pp + p*1024 + e);
        vx += s.x; vy += s.y;
    }
    float b = __ldg(bias + (e>>2));
    vx += b; vy += b;
    if (act == 1) { vx = selu_f(vx); vy = selu_f(vy); }
    else if (act == 2) { vx = fmaxf(vx,0.f); vy = fmaxf(vy,0.f); }
    *(float2*)(outT + e) = make_float2(vx,vy);
    __syncthreads();
}

__device__ __noinline__ void feval(const float* __restrict__ inT, float* __restrict__ outT,
                                   float* __restrict__ aT, float* __restrict__ bT,
                                   float* __restrict__ Pp,
                                   const float* ob1, const float* ob2,
                                   const float* ob3, const float* ob4,
                                   int oc, int q, int tid)
{
    smatvec(g_oWT[0], ob1, inT, aT, Pp, oc, q, tid, 1);
    smatvec(g_oWT[1], ob2, aT,  bT, Pp, oc, q, tid, 1);
    smatvec(g_oWT[2], ob3, bT,  aT, Pp, oc, q, tid, 1);
    smatvec(g_oWT[3], ob4, aT, outT, Pp, oc, q, tid, 0);
}

// ---------------- main persistent kernel ----------------
__global__ __launch_bounds__(NTH, 2)
void node_kernel(const float* __restrict__ x,     const float* __restrict__ meta,
                 const float* __restrict__ eps,   const float* __restrict__ times,
                 const float* __restrict__ doses,
                 const float* __restrict__ gbih,  const float* __restrict__ gbhh,
                 const float* __restrict__ eb1,   const float* __restrict__ eb2,
                 const float* __restrict__ ob1,   const float* __restrict__ ob2,
                 const float* __restrict__ ob3,   const float* __restrict__ ob4,
                 const float* __restrict__ fcW,   const float* __restrict__ fcb,
                 float* __restrict__ out)
{
    extern __shared__ float sm[];
    float* yT   = sm + 0*1024;
    float* tmpT = sm + 1*1024;   // stage input / k7
    float* aT   = sm + 2*1024;   // scratch; reused as reduction buffer + enc mean
    float* bT   = sm + 3*1024;
    float* y5T  = sm + 4*1024;   // also enc std
    float* k1T  = sm + 5*1024;   // reused as x cache during GRU
    float* k2T  = sm + 6*1024;
    float* k3T  = sm + 7*1024;
    float* k4T  = sm + 8*1024;
    float* k5T  = sm + 9*1024;
    float* k6T  = sm +10*1024;
    float* Pp   = sm +11*1024;   // 8*1024 partials (ODE) / 4*2048 (encoder2) / r,z planes (GRU)
    float* red  = aT;
    float* xc   = k1T;

    __shared__ float t_s[4], t1_s[4], dt_s[4], d_s[4], ds_s[4], meta_s[16];
    __shared__ int   act_s[4], accfl[4];

    const int tid  = threadIdx.x;
    const int oc   = tid & 63;       // ODE matvec: column group of 4
    const int q    = tid >> 6;       // ODE matvec: K-chunk 0..7
    const int o    = tid & 255;      // GRU: column
    const int qg   = tid >> 8;       // GRU: 0 -> gates r,z ; 1 -> gate n
    const int wid  = tid >> 5;
    const int lane = tid & 31;
    const int r0   = blockIdx.x * RPB;
    const int e2i  = tid*2;          // my 2 elems in [0,1024)
    const int re0  = e2i & 3;        // rows of my elems: re0, re0+1

    // ---- caches ----
    for (int e = tid; e < 1024; e += NTH) { xc[e] = x[r0*256 + e]; yT[e] = 0.f; }
    if (tid < 16) meta_s[tid] = meta[r0*4 + tid];

    // GRU register weights / biases
    float wA[8], wB[8];
    float bA, bB;
    if (qg == 0) {
#pragma unroll
        for (int c = 0; c < 8; c++) { wA[c] = g_WihT[c*768 + o]; wB[c] = g_WihT[c*768 + o + 256]; }
        bA = gbih[o] + gbhh[o];
        bB = gbih[o+256] + gbhh[o+256];
    } else {
#pragma unroll
        for (int c = 0; c < 8; c++) { wA[c] = g_WihT[c*768 + o + 512]; wB[c] = 0.f; }
        bA = gbhh[o + 512];     // hidden-side n bias (goes in accumulation)
        bB = gbih[o + 512];     // input-side n bias (added with r*hn later)
    }
    __syncthreads();

    // ---------------- Phase A: GRU over 64 timesteps ----------------
    for (int t = 0; t < 64; t++) {
        if (qg == 0) {
            ull ar0 = pack2(bA,bA), ar1 = ar0, az0 = pack2(bB,bB), az1 = az0;
            const float* w1p = g_WhhT + o;
            const float* w2p = g_WhhT + o + 256;
            const float4* h4 = (const float4*)yT;
#pragma unroll 8
            for (int i = 0; i < 256; i++) {
                float wa = __ldg(w1p + i*768), wb = __ldg(w2p + i*768);
                float4 u = h4[i];
                ull u01 = pack2(u.x,u.y), u23 = pack2(u.z,u.w);
                ull wa2 = pack2(wa,wa), wb2 = pack2(wb,wb);
                fma2(ar0,u01,wa2); fma2(ar1,u23,wa2);
                fma2(az0,u01,wb2); fma2(az1,u23,wb2);
            }
            float fr[4], fz[4];
            unpack2(ar0,fr[0],fr[1]); unpack2(ar1,fr[2],fr[3]);
            unpack2(az0,fz[0],fz[1]); unpack2(az1,fz[2],fz[3]);
#pragma unroll
            for (int r = 0; r < 4; r++) {
                float sr = 0.f, sz = 0.f;
#pragma unroll
                for (int c = 0; c < 4; c++) {
                    float xv = xc[r*256 + t*4 + c];
                    sr = fmaf(xv, wA[c], sr); sz = fmaf(xv, wB[c], sz);
                }
#pragma unroll
                for (int c = 0; c < 4; c++) {
                    float mv = meta_s[r*4 + c];
                    sr = fmaf(mv, wA[4+c], sr); sz = fmaf(mv, wB[4+c], sz);
                }
                fr[r] = sigmoid_f(fr[r] + sr);
                fz[r] = sigmoid_f(fz[r] + sz);
            }
            *(float4*)(Pp + o*4)        = make_float4(fr[0],fr[1],fr[2],fr[3]);
            *(float4*)(Pp + 1024 + o*4) = make_float4(fz[0],fz[1],fz[2],fz[3]);
            __syncthreads();
            __syncthreads();
        } else {
            ull an0 = pack2(bA,bA), an1 = an0;
            const float* w3p = g_WhhT + o + 512;
            const float4* h4 = (const float4*)yT;
#pragma unroll 8
            for (int i = 0; i < 256; i++) {
                float wc = __ldg(w3p + i*768);
                float4 u = h4[i];
                ull wc2 = pack2(wc,wc);
                fma2(an0, pack2(u.x,u.y), wc2);
                fma2(an1, pack2(u.z,u.w), wc2);
            }
            float hn[4];
            unpack2(an0,hn[0],hn[1]); unpack2(an1,hn[2],hn[3]);
            float inn[4];
#pragma unroll
            for (int r = 0; r < 4; r++) {
                float s = bB;
#pragma unroll
                for (int c = 0; c < 4; c++) s = fmaf(xc[r*256 + t*4 + c], wA[c], s);
#pragma unroll
                for (int c = 0; c < 4; c++) s = fmaf(meta_s[r*4 + c], wA[4+c], s);
                inn[r] = s;
            }
            __syncthreads();
            float4 R = *(float4*)(Pp + o*4);
            float4 Z = *(float4*)(Pp + 1024 + o*4);
            float4 ho = *(float4*)(yT + o*4);
            float Rr[4] = {R.x,R.y,R.z,R.w};
            float Zr[4] = {Z.x,Z.y,Z.z,Z.w};
            float hr[4] = {ho.x,ho.y,ho.z,ho.w};
            float hnew[4];
#pragma unroll
            for (int r = 0; r < 4; r++) {
                float n = tanhf(inn[r] + Rr[r]*hn[r]);
                hnew[r] = (1.f - Zr[r])*n + Zr[r]*hr[r];
            }
            *(float4*)(yT + o*4) = make_float4(hnew[0],hnew[1],hnew[2],hnew[3]);
            __syncthreads();
        }
    }

    // ---------------- Phase B: encoder -> y0 ----------------
    smatvec(g_e1T, eb1, yT, bT, Pp, oc, q, tid, 2);   // relu into bT
    {
        // 256 -> 512 (mean|std), thread (oc2 in [0,128), q2 in [0,4))
        const int oc2 = tid & 127, q2 = tid >> 7;
        const float4* w4p = (const float4*)g_e2T + q2*64*128 + oc2;
        const float4* in4 = (const float4*)bT;
        ull a0=0,a1=0,a2=0,a3=0,a4=0,a5=0,a6=0,a7=0;
#pragma unroll
        for (int ii = 0; ii < 64; ii++) {
            float4 w = __ldg(w4p + ii*128);
            float4 u = in4[q2*64 + ii];
            ull u01 = pack2(u.x,u.y), u23 = pack2(u.z,u.w);
            ull wx = pack2(w.x,w.x), wy = pack2(w.y,w.y);
            ull wz = pack2(w.z,w.z), ww = pack2(w.w,w.w);
            fma2(a0,u01,wx); fma2(a1,u23,wx);
            fma2(a2,u01,wy); fma2(a3,u23,wy);
            fma2(a4,u01,wz); fma2(a5,u23,wz);
            fma2(a6,u01,ww); fma2(a7,u23,ww);
        }
        float* P = Pp + q2*2048 + oc2*16;
        float f0,f1,f2,f3;
        unpack2(a0,f0,f1); unpack2(a1,f2,f3); *(float4*)(P+0)  = make_float4(f0,f1,f2,f3);
        unpack2(a2,f0,f1); unpack2(a3,f2,f3); *(float4*)(P+4)  = make_float4(f0,f1,f2,f3);
        unpack2(a4,f0,f1); unpack2(a5,f2,f3); *(float4*)(P+8)  = make_float4(f0,f1,f2,f3);
        unpack2(a6,f0,f1); unpack2(a7,f2,f3); *(float4*)(P+12) = make_float4(f0,f1,f2,f3);
        __syncthreads();
        {
            int e = tid*4;
            float4 v = make_float4(0.f,0.f,0.f,0.f);
#pragma unroll
            for (int p = 0; p < 4; p++) {
                float4 s = *(float4*)(Pp + p*2048 + e);
                v.x += s.x; v.y += s.y; v.z += s.z; v.w += s.w;
            }
            float b = __ldg(eb2 + tid);
            v.x += b; v.y += b; v.z += b; v.w += b;
            if (tid < 256) *(float4*)(aT + e) = v;
            else           *(float4*)(y5T + e - 1024) = v;
        }
        __syncthreads();
        {
            int c = e2i >> 2;
            float m0 = aT[e2i], m1 = aT[e2i+1];
            float s0 = y5T[e2i], s1 = y5T[e2i+1];
            float ev0 = __ldg(eps + (r0 + re0)*256 + c);
            float ev1 = __ldg(eps + (r0 + re0 + 1)*256 + c);
            yT[e2i]   = fmaf(ev0, s0, m0);
            yT[e2i+1] = fmaf(ev1, s1, m1);
        }
        __syncthreads();
    }

    // ---------------- Phase C: 4 x dopri5 ----------------
    const float A21 = 0.2f;
    const float A31 = (float)(3.0/40.0),  A32 = (float)(9.0/40.0);
    const float A41 = (float)(44.0/45.0), A42 = (float)(-56.0/15.0), A43 = (float)(32.0/9.0);
    const float A51 = (float)(19372.0/6561.0), A52 = (float)(-25360.0/2187.0),
                A53 = (float)(64448.0/6561.0), A54 = (float)(-212.0/729.0);
    const float A61 = (float)(9017.0/3168.0), A62 = (float)(-355.0/33.0),
                A63 = (float)(46732.0/5247.0), A64 = (float)(49.0/176.0),
                A65 = (float)(-5103.0/18656.0);
    const float BC0 = (float)(35.0/384.0), BC2 = (float)(500.0/1113.0),
                BC3 = (float)(125.0/192.0), BC4 = (float)(-2187.0/6784.0),
                BC5 = (float)(11.0/84.0);
    const float EC0 = (float)(35.0/384.0 - 5179.0/57600.0);
    const float EC2 = (float)(500.0/1113.0 - 7571.0/16695.0);
    const float EC3 = (float)(125.0/192.0 - 393.0/640.0);
    const float EC4 = (float)(-2187.0/6784.0 + 92097.0/339200.0);
    const float EC5 = (float)(11.0/84.0 - 187.0/2100.0);
    const float EC6 = (float)(-1.0/40.0);

    for (int j = 0; j < 4; j++) {
        if (tid < 4) {
            int row = r0 + tid;
            float t0v = times[(j*1024 + row)*2 + 0];
            float t1v = times[(j*1024 + row)*2 + 1];
            t_s[tid]  = t0v;
            t1_s[tid] = t1v;
            dt_s[tid] = fmaxf(t1v - t0v, 1e-6f) * 0.1f;
            ds_s[tid] = (t0v < t1v) ? doses[j*1024 + row] : 0.f;
        }
        __syncthreads();
        {
            float2 y = *(float2*)(yT + e2i);
            y.x += ds_s[re0]; y.y += ds_s[re0 + 1];
            *(float2*)(yT + e2i) = y;
        }

        for (int step = 0; step < 32; step++) {
            int myact = 0;
            if (tid < 4) {
                float tt = t_s[tid], t1v = t1_s[tid];
                myact = (tt < t1v) ? 1 : 0;
                act_s[tid] = myact;
                float rem = fmaxf(t1v - tt, 0.f);
                d_s[tid] = fminf(fmaxf(dt_s[tid], 0.f), rem);
            }
            if (!__syncthreads_or(myact)) break;   // uniform exit

            const float d0 = d_s[re0], d1 = d_s[re0 + 1];

#define COMB2(DST, EX, EY) do { \
            float2 _y = *(float2*)(yT + e2i); \
            float2 _t; \
            _t.x = fmaf(d0, (EX), _y.x); _t.y = fmaf(d1, (EY), _y.y); \
            *(float2*)(DST + e2i) = _t; } while(0)

            feval(yT, k1T, aT, bT, Pp, ob1, ob2, ob3, ob4, oc, q, tid);
            {
                float2 a = *(float2*)(k1T + e2i);
                COMB2(tmpT, A21*a.x, A21*a.y);
            }
            __syncthreads();
            feval(tmpT, k2T, aT, bT, Pp, ob1, ob2, ob3, ob4, oc, q, tid);
            {
                float2 a = *(float2*)(k1T + e2i); float2 b = *(float2*)(k2T + e2i);
                COMB2(tmpT, A31*a.x + A32*b.x, A31*a.y + A32*b.y);
            }
            __syncthreads();
            feval(tmpT, k3T, aT, bT, Pp, ob1, ob2, ob3, ob4, oc, q, tid);
            {
                float2 a = *(float2*)(k1T + e2i); float2 b = *(float2*)(k2T + e2i);
                float2 c = *(float2*)(k3T + e2i);
                COMB2(tmpT, A41*a.x + A42*b.x + A43*c.x,
                            A41*a.y + A42*b.y + A43*c.y);
            }
            __syncthreads();
            feval(tmpT, k4T, aT, bT, Pp, ob1, ob2, ob3, ob4, oc, q, tid);
            {
                float2 a = *(float2*)(k1T + e2i); float2 b = *(float2*)(k2T + e2i);
                float2 c = *(float2*)(k3T + e2i); float2 e = *(float2*)(k4T + e2i);
                COMB2(tmpT, A51*a.x + A52*b.x + A53*c.x + A54*e.x,
                            A51*a.y + A52*b.y + A53*c.y + A54*e.y);
            }
            __syncthreads();
            feval(tmpT, k5T, aT, bT, Pp, ob1, ob2, ob3, ob4, oc, q, tid);
            {
                float2 a = *(float2*)(k1T + e2i); float2 b = *(float2*)(k2T + e2i);
                float2 c = *(float2*)(k3T + e2i); float2 e = *(float2*)(k4T + e2i);
                float2 f = *(float2*)(k5T + e2i);
                COMB2(tmpT, A61*a.x + A62*b.x + A63*c.x + A64*e.x + A65*f.x,
                            A61*a.y + A62*b.y + A63*c.y + A64*e.y + A65*f.y);
            }
            __syncthreads();
            feval(tmpT, k6T, aT, bT, Pp, ob1, ob2, ob3, ob4, oc, q, tid);
            {
                float2 a = *(float2*)(k1T + e2i); float2 c = *(float2*)(k3T + e2i);
                float2 e = *(float2*)(k4T + e2i); float2 f = *(float2*)(k5T + e2i);
                float2 g6 = *(float2*)(k6T + e2i);
                COMB2(y5T, BC0*a.x + BC2*c.x + BC3*e.x + BC4*f.x + BC5*g6.x,
                           BC0*a.y + BC2*c.y + BC3*e.y + BC4*f.y + BC5*g6.y);
            }
            __syncthreads();
            feval(y5T, tmpT, aT, bT, Pp, ob1, ob2, ob3, ob4, oc, q, tid);   // k7 -> tmpT

            // error-norm contributions -> red (== aT, free now)
            {
                float2 a = *(float2*)(k1T + e2i); float2 c = *(float2*)(k3T + e2i);
                float2 e = *(float2*)(k4T + e2i); float2 f = *(float2*)(k5T + e2i);
                float2 g6 = *(float2*)(k6T + e2i); float2 s7 = *(float2*)(tmpT + e2i);
                float2 y = *(float2*)(yT + e2i);  float2 y5 = *(float2*)(y5T + e2i);
                float ex = EC0*a.x + EC2*c.x + EC3*e.x + EC4*f.x + EC5*g6.x + EC6*s7.x;
                float ey = EC0*a.y + EC2*c.y + EC3*e.y + EC4*f.y + EC5*g6.y + EC6*s7.y;
                float qx = d0*ex / (1e-6f + 1e-3f*fmaxf(fabsf(y.x), fabsf(y5.x)));
                float qy = d1*ey / (1e-6f + 1e-3f*fmaxf(fabsf(y.y), fabsf(y5.y)));
                *(float2*)(red + e2i) = make_float2(qx*qx, qy*qy);
            }
            __syncthreads();
            if (wid < 4) {
                int r = wid;
                const float* rp = red + r;
                float s = 0.f;
#pragma unroll
                for (int c = 0; c < 8; c++) s += rp[(lane + 32*c)*4];
                s += __shfl_xor_sync(0xffffffffu, s, 16);
                s += __shfl_xor_sync(0xffffffffu, s, 8);
                s += __shfl_xor_sync(0xffffffffu, s, 4);
                s += __shfl_xor_sync(0xffffffffu, s, 2);
                s += __shfl_xor_sync(0xffffffffu, s, 1);
                if (lane == 0) {
                    float en = sqrtf(s * (1.f/256.f));
                    int active = act_s[r];
                    int acc = (en <= 1.f) && active;
                    accfl[r] = acc;
                    float dtc = d_s[r];
                    if (acc) t_s[r] += dtc;
                    if (active) {
                        float fac = 0.9f * powf(en + 1e-10f, -0.2f);
                        fac = fminf(fmaxf(fac, 0.2f), 10.f);
                        dt_s[r] = fmaxf(dtc, 1e-8f) * fac;
                    }
                }
            }
            __syncthreads();
            {
                float2 y = *(float2*)(yT + e2i);
                float2 y5 = *(float2*)(y5T + e2i);
                if (accfl[re0])     y.x = y5.x;
                if (accfl[re0 + 1]) y.y = y5.y;
                *(float2*)(yT + e2i) = y;
            }
            __syncthreads();
#undef COMB2
        }
    }

    // ---------------- Phase D: linear head ----------------
    {
        float fcw = __ldg(fcW + (e2i >> 2));
        float2 y = *(float2*)(yT + e2i);
        *(float2*)(red + e2i) = make_float2(y.x*fcw, y.y*fcw);
        __syncthreads();
        if (wid < 4) {
            int r = wid;
            const float* rp = red + r;
            float s = 0.f;
#pragma unroll
            for (int c = 0; c < 8; c++) s += rp[(lane + 32*c)*4];
            s += __shfl_xor_sync(0xffffffffu, s, 16);
            s += __shfl_xor_sync(0xffffffffu, s, 8);
            s += __shfl_xor_sync(0xffffffffu, s, 4);
            s += __shfl_xor_sync(0xffffffffu, s, 2);
            s += __shfl_xor_sync(0xffffffffu, s, 1);
            if (lane == 0) {
                s += fcb[0];
#pragma unroll
                for (int c = 0; c < 4; c++) s += meta_s[r*4 + c] * fcW[256 + c];
                out[r0 + r] = s;
            }
        }
    }
}

extern "C" void kernel_launch(void* const* d_in, const int* in_sizes, int n_in,
                              void* d_out, int out_size)
{
    const float* x     = (const float*)d_in[0];
    const float* meta  = (const float*)d_in[1];
    const float* eps   = (const float*)d_in[2];
    const float* times = (const float*)d_in[3];
    const float* doses = (const float*)d_in[4];
    const float* gWih  = (const float*)d_in[5];
    const float* gWhh  = (const float*)d_in[6];
    const float* gbih  = (const float*)d_in[7];
    const float* gbhh  = (const float*)d_in[8];
    const float* eW1   = (const float*)d_in[9];
    const float* eb1   = (const float*)d_in[10];
    const float* eW2   = (const float*)d_in[11];
    const float* eb2   = (const float*)d_in[12];
    const float* oW1   = (const float*)d_in[13];
    const float* ob1   = (const float*)d_in[14];
    const float* oW2   = (const float*)d_in[15];
    const float* ob2   = (const float*)d_in[16];
    const float* oW3   = (const float*)d_in[17];
    const float* ob3   = (const float*)d_in[18];
    const float* oW4   = (const float*)d_in[19];
    const float* ob4   = (const float*)d_in[20];
    const float* fcW   = (const float*)d_in[21];
    const float* fcb   = (const float*)d_in[22];
    float* out = (float*)d_out;

    prep_kernel<<<768, 256>>>(gWih, gWhh, eW1, eW2, oW1, oW2, oW3, oW4);

    const int smem_bytes = 19 * 1024 * sizeof(float);   // 77824
    static int attr_done = 0;
    if (!attr_done) {
        cudaFuncSetAttribute(node_kernel, cudaFuncAttributeMaxDynamicSharedMemorySize, smem_bytes);
        attr_done = 1;
    }
    node_kernel<<<256, NTH, smem_bytes>>>(x, meta, eps, times, doses,
                                          gbih, gbhh, eb1, eb2,
                                          ob1, ob2, ob3, ob4, fcW, fcb, out);
}

// round 8
// speedup vs baseline: 1.5161x; 1.0221x over previous
#include <cuda_runtime.h>
#include <math.h>

#define NTH 1024
#define RPB 8

typedef unsigned long long ull;

// ---------------- transposed/packed weight scratch (device globals) ----
// Packed 256x256 layout "P": float pair slot pc in [0,128): (col pc, col pc+128)
//   dst[i*256 + 2*pc + 0] = W[pc][i] ; dst[i*256 + 2*pc + 1] = W[pc+128][i]
__device__ float g_WrzT[2*256*256];  // float2 [i*256+o] = (Wr[o][i], Wz[o][i])
__device__ float g_WnT [256*256];    // [i*256+o]
__device__ float g_WihT[8*768];      // [ii*768+o]
__device__ float g_e1P [256*256];
__device__ float g_e2mP[256*256];
__device__ float g_e2sP[256*256];
__device__ float g_oWP [4][256*256];

__global__ void prep_kernel(const float* __restrict__ Wih, const float* __restrict__ Whh,
                            const float* __restrict__ eW1, const float* __restrict__ eW2,
                            const float* __restrict__ oW1, const float* __restrict__ oW2,
                            const float* __restrict__ oW3, const float* __restrict__ oW4)
{
    int idx = blockIdx.x*blockDim.x + threadIdx.x;
    if (idx >= 65536) return;
    int o = idx >> 8, i = idx & 255;
    // GRU hidden weights
    ((float2*)g_WrzT)[i*256 + o] = make_float2(Whh[o*256 + i], Whh[(o+256)*256 + i]);
    g_WnT[i*256 + o] = Whh[(o+512)*256 + i];
    // packed dest for 256x256 matrices
    int pd = i*256 + ((o < 128) ? (2*o) : (2*(o-128) + 1));
    g_e1P [pd] = eW1[o*256 + i];
    g_e2mP[pd] = eW2[o*256 + i];
    g_e2sP[pd] = eW2[(o+256)*256 + i];
    g_oWP[0][pd] = oW1[o*256 + i];
    g_oWP[1][pd] = oW2[o*256 + i];
    g_oWP[2][pd] = oW3[o*256 + i];
    g_oWP[3][pd] = oW4[o*256 + i];
    // GRU input weights (768 x 8)
    if (idx < 6144) { int oo = idx / 8, ii = idx % 8; g_WihT[ii*768 + oo] = Wih[idx]; }
}

// ---------------- f32x2 helpers ----------------
__device__ __forceinline__ ull pack2(float a, float b){
    ull r; asm("mov.b64 %0, {%1, %2};" : "=l"(r) : "f"(a), "f"(b)); return r;
}
__device__ __forceinline__ void unpack2(ull v, float& a, float& b){
    asm("mov.b64 {%0, %1}, %2;" : "=f"(a), "=f"(b) : "l"(v));
}
__device__ __forceinline__ void fma2(ull& acc, ull a, ull b){
    asm("fma.rn.f32x2 %0, %1, %2, %0;" : "+l"(acc) : "l"(a), "l"(b));
}

__device__ __forceinline__ float selu_f(float x){
    const float sc = 1.0507009873554805f, al = 1.6732632423543772f;
    return x > 0.f ? sc*x : sc*(al*expm1f(x));
}
__device__ __forceinline__ float sigmoid_f(float x){ return 1.f/(1.f+expf(-x)); }

// Activation layout (8 rows x 256 cols, 2048 floats):
//   elem (r, c) at buf[(r>>2)*1024 + c*4 + (r&3)]
// Split-K matvec: thread (oc in [0,128), q in [0,8)) owns cols {oc, oc+128},
// all 8 rows, i in [q*32, q*32+32). Weights pre-packed per "P" scheme.
__device__ __noinline__ void smatvec8(const float* __restrict__ WT,
                                      const float* __restrict__ bias,
                                      const float* __restrict__ inT,
                                      float* __restrict__ outT,
                                      float* __restrict__ Pp,
                                      int oc, int q, int tid, int act)
{
    const float4* in4 = (const float4*)inT;
    const float2* w2p = (const float2*)WT + q*32*128 + oc;
    ull a00=0,a01=0,a02=0,a03=0;   // col oc     : (r0r1)(r2r3)(r4r5)(r6r7)
    ull a10=0,a11=0,a12=0,a13=0;   // col oc+128
#pragma unroll 8
    for (int ii = 0; ii < 32; ii++) {
        int i = q*32 + ii;
        float2 w = __ldg(w2p + ii*128);
        float4 u0 = in4[i];         // rows 0-3
        float4 u1 = in4[256 + i];   // rows 4-7
        ull p0 = pack2(u0.x,u0.y), p1 = pack2(u0.z,u0.w);
        ull p2 = pack2(u1.x,u1.y), p3 = pack2(u1.z,u1.w);
        ull wx = pack2(w.x,w.x), wy = pack2(w.y,w.y);
        fma2(a00,p0,wx); fma2(a01,p1,wx); fma2(a02,p2,wx); fma2(a03,p3,wx);
        fma2(a10,p0,wy); fma2(a11,p1,wy); fma2(a12,p2,wy); fma2(a13,p3,wy);
    }
    float* P = Pp + q*2048;
    float f0,f1,f2,f3;
    unpack2(a00,f0,f1); unpack2(a01,f2,f3); *(float4*)(P + oc*4)         = make_float4(f0,f1,f2,f3);
    unpack2(a10,f0,f1); unpack2(a11,f2,f3); *(float4*)(P + 512 + oc*4)   = make_float4(f0,f1,f2,f3);
    unpack2(a02,f0,f1); unpack2(a03,f2,f3); *(float4*)(P + 1024 + oc*4)  = make_float4(f0,f1,f2,f3);
    unpack2(a12,f0,f1); unpack2(a13,f2,f3); *(float4*)(P + 1536 + oc*4)  = make_float4(f0,f1,f2,f3);
    __syncthreads();
    const int e = tid*2;
    float vx = 0.f, vy = 0.f;
#pragma unroll
    for (int p = 0; p < 8; p++) {
        float2 s = *(float2*)(Pp + p*2048 + e);
        vx += s.x; vy += s.y;
    }
    float b = __ldg(bias + ((e & 1023) >> 2));
    vx += b; vy += b;
    if (act == 1) { vx = selu_f(vx); vy = selu_f(vy); }
    else if (act == 2) { vx = fmaxf(vx,0.f); vy = fmaxf(vy,0.f); }
    *(float2*)(outT + e) = make_float2(vx,vy);
    __syncthreads();
}

__device__ __noinline__ void feval(const float* __restrict__ inT, float* __restrict__ outT,
                                   float* __restrict__ aT, float* __restrict__ bT,
                                   float* __restrict__ Pp,
                                   const float* ob1, const float* ob2,
                                   const float* ob3, const float* ob4,
                                   int oc, int q, int tid)
{
    smatvec8(g_oWP[0], ob1, inT, aT, Pp, oc, q, tid, 1);
    smatvec8(g_oWP[1], ob2, aT,  bT, Pp, oc, q, tid, 1);
    smatvec8(g_oWP[2], ob3, bT,  aT, Pp, oc, q, tid, 1);
    smatvec8(g_oWP[3], ob4, aT, outT, Pp, oc, q, tid, 0);
}

// ---------------- main persistent kernel ----------------
__global__ __launch_bounds__(NTH, 1)
void node_kernel(const float* __restrict__ x,     const float* __restrict__ meta,
                 const float* __restrict__ eps,   const float* __restrict__ times,
                 const float* __restrict__ doses,
                 const float* __restrict__ gbih,  const float* __restrict__ gbhh,
                 const float* __restrict__ eb1,   const float* __restrict__ eb2,
                 const float* __restrict__ ob1,   const float* __restrict__ ob2,
                 const float* __restrict__ ob3,   const float* __restrict__ ob4,
                 const float* __restrict__ fcW,   const float* __restrict__ fcb,
                 float* __restrict__ out)
{
    extern __shared__ float sm[];
    float* yT   = sm + 0*2048;
    float* tmpT = sm + 1*2048;   // stage input / k7
    float* aT   = sm + 2*2048;   // scratch; also "red" + encoder mean
    float* bT   = sm + 3*2048;
    float* y5T  = sm + 4*2048;   // also encoder std
    float* k1T  = sm + 5*2048;   // x cache during GRU
    float* k2T  = sm + 6*2048;
    float* k3T  = sm + 7*2048;
    float* k4T  = sm + 8*2048;
    float* k5T  = sm + 9*2048;
    float* k6T  = sm +10*2048;
    float* Pp   = sm +11*2048;   // 8*2048 split-K partials; GRU gate planes
    float* red  = aT;
    float* xc   = k1T;

    __shared__ float t_s[8], t1_s[8], dt_s[8], d_s[8], ds_s[8], meta_s[32];
    __shared__ int   act_s[8], accfl[8];

    const int tid  = threadIdx.x;
    const int oc   = tid & 127;      // ODE: column pair {oc, oc+128}
    const int q    = tid >> 7;       // ODE: K-chunk 0..7
    const int ht   = tid & 511;      // GRU: index within half
    const int h    = tid >> 9;       // GRU: row half (rows 4h..4h+3)
    const int o    = ht & 255;       // GRU: column
    const int qg   = ht >> 8;        // GRU: 0 -> gates r,z ; 1 -> gate n
    const int wid  = tid >> 5;
    const int lane = tid & 31;
    const int r0   = blockIdx.x * RPB;
    const int e2i  = tid*2;                          // my 2 elems in [0,2048)
    const int re0  = ((e2i >> 10) << 2) | (e2i & 3); // rows: re0, re0+1

    // ---- caches ----
    for (int e = tid; e < 2048; e += NTH) { xc[e] = x[r0*256 + e]; yT[e] = 0.f; }
    if (tid < 32) meta_s[tid] = meta[r0*4 + tid];

    // GRU register weights / biases
    float wA[8], wB[8];
    float bA, bB, bN = 0.f;
    if (qg == 0) {
#pragma unroll
        for (int c = 0; c < 8; c++) { wA[c] = g_WihT[c*768 + o]; wB[c] = g_WihT[c*768 + o + 256]; }
        bA = gbih[o] + gbhh[o];
        bB = gbih[o+256] + gbhh[o+256];
    } else {
#pragma unroll
        for (int c = 0; c < 8; c++) { wA[c] = g_WihT[c*768 + o + 512]; wB[c] = 0.f; }
        bA = gbhh[o + 512];     // hidden-side n bias (in accumulation)
        bN = gbih[o + 512];     // input-side n bias
        bB = 0.f;
    }
    __syncthreads();

    // ---------------- Phase A: GRU over 64 timesteps (two 4-row halves) ----
    for (int t = 0; t < 64; t++) {
        if (qg == 0) {
            ull ar0 = pack2(bA,bA), ar1 = ar0, az0 = pack2(bB,bB), az1 = az0;
            const float2* wrz = (const float2*)g_WrzT + o;
            const float4* h4 = (const float4*)(yT + h*1024);
#pragma unroll 8
            for (int i = 0; i < 256; i++) {
                float2 w = __ldg(wrz + i*256);
                float4 u = h4[i];
                ull u01 = pack2(u.x,u.y), u23 = pack2(u.z,u.w);
                ull wx = pack2(w.x,w.x), wy = pack2(w.y,w.y);
                fma2(ar0,u01,wx); fma2(ar1,u23,wx);
                fma2(az0,u01,wy); fma2(az1,u23,wy);
            }
            float fr[4], fz[4];
            unpack2(ar0,fr[0],fr[1]); unpack2(ar1,fr[2],fr[3]);
            unpack2(az0,fz[0],fz[1]); unpack2(az1,fz[2],fz[3]);
#pragma unroll
            for (int k = 0; k < 4; k++) {
                int r = 4*h + k;
                float sr = 0.f, sz = 0.f;
#pragma unroll
                for (int c = 0; c < 4; c++) {
                    float xv = xc[r*256 + t*4 + c];
                    sr = fmaf(xv, wA[c], sr); sz = fmaf(xv, wB[c], sz);
                }
#pragma unroll
                for (int c = 0; c < 4; c++) {
                    float mv = meta_s[r*4 + c];
                    sr = fmaf(mv, wA[4+c], sr); sz = fmaf(mv, wB[4+c], sz);
                }
                fr[k] = sigmoid_f(fr[k] + sr);
                fz[k] = sigmoid_f(fz[k] + sz);
            }
            *(float4*)(Pp + h*2048 + o*4)        = make_float4(fr[0],fr[1],fr[2],fr[3]);
            *(float4*)(Pp + h*2048 + 1024 + o*4) = make_float4(fz[0],fz[1],fz[2],fz[3]);
            __syncthreads();
            __syncthreads();
        } else {
            ull an0 = pack2(bA,bA), an1 = an0;
            const float* wn = g_WnT + o;
            const float4* h4 = (const float4*)(yT + h*1024);
#pragma unroll 8
            for (int i = 0; i < 256; i++) {
                float w = __ldg(wn + i*256);
                float4 u = h4[i];
                ull w2 = pack2(w,w);
                fma2(an0, pack2(u.x,u.y), w2);
                fma2(an1, pack2(u.z,u.w), w2);
            }
            float hn[4];
            unpack2(an0,hn[0],hn[1]); unpack2(an1,hn[2],hn[3]);
            float inn[4];
#pragma unroll
            for (int k = 0; k < 4; k++) {
                int r = 4*h + k;
                float s = bN;
#pragma unroll
                for (int c = 0; c < 4; c++) s = fmaf(xc[r*256 + t*4 + c], wA[c], s);
#pragma unroll
                for (int c = 0; c < 4; c++) s = fmaf(meta_s[r*4 + c], wA[4+c], s);
                inn[k] = s;
            }
            __syncthreads();
            float4 R  = *(float4*)(Pp + h*2048 + o*4);
            float4 Z  = *(float4*)(Pp + h*2048 + 1024 + o*4);
            float4 ho = *(float4*)(yT + h*1024 + o*4);
            float Rr[4] = {R.x,R.y,R.z,R.w};
            float Zr[4] = {Z.x,Z.y,Z.z,Z.w};
            float hr[4] = {ho.x,ho.y,ho.z,ho.w};
            float hnew[4];
#pragma unroll
            for (int k = 0; k < 4; k++) {
                float n = tanhf(inn[k] + Rr[k]*hn[k]);
                hnew[k] = (1.f - Zr[k])*n + Zr[k]*hr[k];
            }
            *(float4*)(yT + h*1024 + o*4) = make_float4(hnew[0],hnew[1],hnew[2],hnew[3]);
            __syncthreads();
        }
    }

    // ---------------- Phase B: encoder -> y0 ----------------
    smatvec8(g_e1P,  eb1,       yT, bT,  Pp, oc, q, tid, 2);  // relu
    smatvec8(g_e2mP, eb2,       bT, aT,  Pp, oc, q, tid, 0);  // mean
    smatvec8(g_e2sP, eb2 + 256, bT, y5T, Pp, oc, q, tid, 0);  // std
    {
        int c = (e2i & 1023) >> 2;
        float m0 = aT[e2i], m1 = aT[e2i+1];
        float s0 = y5T[e2i], s1 = y5T[e2i+1];
        float ev0 = __ldg(eps + (r0 + re0)*256 + c);
        float ev1 = __ldg(eps + (r0 + re0 + 1)*256 + c);
        yT[e2i]   = fmaf(ev0, s0, m0);
        yT[e2i+1] = fmaf(ev1, s1, m1);
    }
    __syncthreads();

    // ---------------- Phase C: 4 x dopri5 ----------------
    const float A21 = 0.2f;
    const float A31 = (float)(3.0/40.0),  A32 = (float)(9.0/40.0);
    const float A41 = (float)(44.0/45.0), A42 = (float)(-56.0/15.0), A43 = (float)(32.0/9.0);
    const float A51 = (float)(19372.0/6561.0), A52 = (float)(-25360.0/2187.0),
                A53 = (float)(64448.0/6561.0), A54 = (float)(-212.0/729.0);
    const float A61 = (float)(9017.0/3168.0), A62 = (float)(-355.0/33.0),
                A63 = (float)(46732.0/5247.0), A64 = (float)(49.0/176.0),
                A65 = (float)(-5103.0/18656.0);
    const float BC0 = (float)(35.0/384.0), BC2 = (float)(500.0/1113.0),
                BC3 = (float)(125.0/192.0), BC4 = (float)(-2187.0/6784.0),
                BC5 = (float)(11.0/84.0);
    const float EC0 = (float)(35.0/384.0 - 5179.0/57600.0);
    const float EC2 = (float)(500.0/1113.0 - 7571.0/16695.0);
    const float EC3 = (float)(125.0/192.0 - 393.0/640.0);
    const float EC4 = (float)(-2187.0/6784.0 + 92097.0/339200.0);
    const float EC5 = (float)(11.0/84.0 - 187.0/2100.0);
    const float EC6 = (float)(-1.0/40.0);

    for (int j = 0; j < 4; j++) {
        if (tid < 8) {
            int row = r0 + tid;
            float t0v = times[(j*1024 + row)*2 + 0];
            float t1v = times[(j*1024 + row)*2 + 1];
            t_s[tid]  = t0v;
            t1_s[tid] = t1v;
            dt_s[tid] = fmaxf(t1v - t0v, 1e-6f) * 0.1f;
            ds_s[tid] = (t0v < t1v) ? doses[j*1024 + row] : 0.f;
        }
        __syncthreads();
        {
            float2 y = *(float2*)(yT + e2i);
            y.x += ds_s[re0]; y.y += ds_s[re0 + 1];
            *(float2*)(yT + e2i) = y;
        }

        for (int step = 0; step < 32; step++) {
            int myact = 0;
            if (tid < 8) {
                float tt = t_s[tid], t1v = t1_s[tid];
                myact = (tt < t1v) ? 1 : 0;
                act_s[tid] = myact;
                float rem = fmaxf(t1v - tt, 0.f);
                d_s[tid] = fminf(fmaxf(dt_s[tid], 0.f), rem);
            }
            if (!__syncthreads_or(myact)) break;   // uniform exit

            const float d0 = d_s[re0], d1 = d_s[re0 + 1];

#define COMB2(DST, EX, EY) do { \
            float2 _y = *(float2*)(yT + e2i); \
            float2 _t; \
            _t.x = fmaf(d0, (EX), _y.x); _t.y = fmaf(d1, (EY), _y.y); \
            *(float2*)(DST + e2i) = _t; } while(0)

            feval(yT, k1T, aT, bT, Pp, ob1, ob2, ob3, ob4, oc, q, tid);
            {
                float2 a = *(float2*)(k1T + e2i);
                COMB2(tmpT, A21*a.x, A21*a.y);
            }
            __syncthreads();
            feval(tmpT, k2T, aT, bT, Pp, ob1, ob2, ob3, ob4, oc, q, tid);
            {
                float2 a = *(float2*)(k1T + e2i); float2 b = *(float2*)(k2T + e2i);
                COMB2(tmpT, A31*a.x + A32*b.x, A31*a.y + A32*b.y);
            }
            __syncthreads();
            feval(tmpT, k3T, aT, bT, Pp, ob1, ob2, ob3, ob4, oc, q, tid);
            {
                float2 a = *(float2*)(k1T + e2i); float2 b = *(float2*)(k2T + e2i);
                float2 c = *(float2*)(k3T + e2i);
                COMB2(tmpT, A41*a.x + A42*b.x + A43*c.x,
                            A41*a.y + A42*b.y + A43*c.y);
            }
            __syncthreads();
            feval(tmpT, k4T, aT, bT, Pp, ob1, ob2, ob3, ob4, oc, q, tid);
            {
                float2 a = *(float2*)(k1T + e2i); float2 b = *(float2*)(k2T + e2i);
                float2 c = *(float2*)(k3T + e2i); float2 e = *(float2*)(k4T + e2i);
                COMB2(tmpT, A51*a.x + A52*b.x + A53*c.x + A54*e.x,
                            A51*a.y + A52*b.y + A53*c.y + A54*e.y);
            }
            __syncthreads();
            feval(tmpT, k5T, aT, bT, Pp, ob1, ob2, ob3, ob4, oc, q, tid);
            {
                float2 a = *(float2*)(k1T + e2i); float2 b = *(float2*)(k2T + e2i);
                float2 c = *(float2*)(k3T + e2i); float2 e = *(float2*)(k4T + e2i);
                float2 f = *(float2*)(k5T + e2i);
                COMB2(tmpT, A61*a.x + A62*b.x + A63*c.x + A64*e.x + A65*f.x,
                            A61*a.y + A62*b.y + A63*c.y + A64*e.y + A65*f.y);
            }
            __syncthreads();
            feval(tmpT, k6T, aT, bT, Pp, ob1, ob2, ob3, ob4, oc, q, tid);
            {
                float2 a = *(float2*)(k1T + e2i); float2 c = *(float2*)(k3T + e2i);
                float2 e = *(float2*)(k4T + e2i); float2 f = *(float2*)(k5T + e2i);
                float2 g6 = *(float2*)(k6T + e2i);
                COMB2(y5T, BC0*a.x + BC2*c.x + BC3*e.x + BC4*f.x + BC5*g6.x,
                           BC0*a.y + BC2*c.y + BC3*e.y + BC4*f.y + BC5*g6.y);
            }
            __syncthreads();
            feval(y5T, tmpT, aT, bT, Pp, ob1, ob2, ob3, ob4, oc, q, tid);   // k7 -> tmpT

            // error-norm contributions -> red (== aT, free now)
            {
                float2 a = *(float2*)(k1T + e2i); float2 c = *(float2*)(k3T + e2i);
                float2 e = *(float2*)(k4T + e2i); float2 f = *(float2*)(k5T + e2i);
                float2 g6 = *(float2*)(k6T + e2i); float2 s7 = *(float2*)(tmpT + e2i);
                float2 y = *(float2*)(yT + e2i);  float2 y5 = *(float2*)(y5T + e2i);
                float ex = EC0*a.x + EC2*c.x + EC3*e.x + EC4*f.x + EC5*g6.x + EC6*s7.x;
                float ey = EC0*a.y + EC2*c.y + EC3*e.y + EC4*f.y + EC5*g6.y + EC6*s7.y;
                float qx = d0*ex / (1e-6f + 1e-3f*fmaxf(fabsf(y.x), fabsf(y5.x)));
                float qy = d1*ey / (1e-6f + 1e-3f*fmaxf(fabsf(y.y), fabsf(y5.y)));
                *(float2*)(red + e2i) = make_float2(qx*qx, qy*qy);
            }
            __syncthreads();
            if (wid < 8) {
                int r = wid;
                const float* rp = red + ((r>>2)<<10) + (r&3);
                float s = 0.f;
#pragma unroll
                for (int c = 0; c < 8; c++) s += rp[(lane + 32*c)*4];
                s += __shfl_xor_sync(0xffffffffu, s, 16);
                s += __shfl_xor_sync(0xffffffffu, s, 8);
                s += __shfl_xor_sync(0xffffffffu, s, 4);
                s += __shfl_xor_sync(0xffffffffu, s, 2);
                s += __shfl_xor_sync(0xffffffffu, s, 1);
                if (lane == 0) {
                    float en = sqrtf(s * (1.f/256.f));
                    int active = act_s[r];
                    int acc = (en <= 1.f) && active;
                    accfl[r] = acc;
                    float dtc = d_s[r];
                    if (acc) t_s[r] += dtc;
                    if (active) {
                        float fac = 0.9f * powf(en + 1e-10f, -0.2f);
                        fac = fminf(fmaxf(fac, 0.2f), 10.f);
                        dt_s[r] = fmaxf(dtc, 1e-8f) * fac;
                    }
                }
            }
            __syncthreads();
            {
                float2 y = *(float2*)(yT + e2i);
                float2 y5 = *(float2*)(y5T + e2i);
                if (accfl[re0])     y.x = y5.x;
                if (accfl[re0 + 1]) y.y = y5.y;
                *(float2*)(yT + e2i) = y;
            }
            __syncthreads();
#undef COMB2
        }
    }

    // ---------------- Phase D: linear head ----------------
    {
        float fcw = __ldg(fcW + ((e2i & 1023) >> 2));
        float2 y = *(float2*)(yT + e2i);
        *(float2*)(red + e2i) = make_float2(y.x*fcw, y.y*fcw);
        __syncthreads();
        if (wid < 8) {
            int r = wid;
            const float* rp = red + ((r>>2)<<10) + (r&3);
            float s = 0.f;
#pragma unroll
            for (int c = 0; c < 8; c++) s += rp[(lane + 32*c)*4];
            s += __shfl_xor_sync(0xffffffffu, s, 16);
            s += __shfl_xor_sync(0xffffffffu, s, 8);
            s += __shfl_xor_sync(0xffffffffu, s, 4);
            s += __shfl_xor_sync(0xffffffffu, s, 2);
            s += __shfl_xor_sync(0xffffffffu, s, 1);
            if (lane == 0) {
                s += fcb[0];
#pragma unroll
                for (int c = 0; c < 4; c++) s += meta_s[r*4 + c] * fcW[256 + c];
                out[r0 + r] = s;
            }
        }
    }
}

extern "C" void kernel_launch(void* const* d_in, const int* in_sizes, int n_in,
                              void* d_out, int out_size)
{
    const float* x     = (const float*)d_in[0];
    const float* meta  = (const float*)d_in[1];
    const float* eps   = (const float*)d_in[2];
    const float* times = (const float*)d_in[3];
    const float* doses = (const float*)d_in[4];
    const float* gWih  = (const float*)d_in[5];
    const float* gWhh  = (const float*)d_in[6];
    const float* gbih  = (const float*)d_in[7];
    const float* gbhh  = (const float*)d_in[8];
    const float* eW1   = (const float*)d_in[9];
    const float* eb1   = (const float*)d_in[10];
    const float* eW2   = (const float*)d_in[11];
    const float* eb2   = (const float*)d_in[12];
    const float* oW1   = (const float*)d_in[13];
    const float* ob1   = (const float*)d_in[14];
    const float* oW2   = (const float*)d_in[15];
    const float* ob2   = (const float*)d_in[16];
    const float* oW3   = (const float*)d_in[17];
    const float* ob3   = (const float*)d_in[18];
    const float* oW4   = (const float*)d_in[19];
    const float* ob4   = (const float*)d_in[20];
    const float* fcW   = (const float*)d_in[21];
    const float* fcb   = (const float*)d_in[22];
    float* out = (float*)d_out;

    prep_kernel<<<256, 256>>>(gWih, gWhh, eW1, eW2, oW1, oW2, oW3, oW4);

    const int smem_bytes = (11*2048 + 8*2048) * sizeof(float);   // 155648
    static int attr_done = 0;
    if (!attr_done) {
        cudaFuncSetAttribute(node_kernel, cudaFuncAttributeMaxDynamicSharedMemorySize, smem_bytes);
        attr_done = 1;
    }
    node_kernel<<<128, NTH, smem_bytes>>>(x, meta, eps, times, doses,
                                          gbih, gbhh, eb1, eb2,
                                          ob1, ob2, ob3, ob4, fcW, fcb, out);
}

// round 9
// speedup vs baseline: 1.5960x; 1.0527x over previous
#include <cuda_runtime.h>
#include <cuda_fp16.h>
#include <math.h>

#define NTH 1024
#define RPB 8

typedef unsigned long long ull;

// ---------------- transposed/packed weight scratch (device globals) ----
// Packed 256x256 layout "P": pair slot pc in [0,128): (col pc, col pc+128)
//   dst[i*256 + 2*pc + 0] = W[pc][i] ; dst[i*256 + 2*pc + 1] = W[pc+128][i]
__device__ float  g_WrzT[2*256*256];   // float2 [i*256+o] = (Wr[o][i], Wz[o][i])
__device__ float  g_WnT [256*256];     // [i*256+o]
__device__ float  g_WihT[8*768];       // [ii*768+o]
__device__ float  g_e1P [256*256];
__device__ float  g_e2mP[256*256];
__device__ float  g_e2sP[256*256];
__device__ __half g_oWH [4][256*256];  // ODE weights fp16, "P" packing

__global__ void prep_kernel(const float* __restrict__ Wih, const float* __restrict__ Whh,
                            const float* __restrict__ eW1, const float* __restrict__ eW2,
                            const float* __restrict__ oW1, const float* __restrict__ oW2,
                            const float* __restrict__ oW3, const float* __restrict__ oW4)
{
    int idx = blockIdx.x*blockDim.x + threadIdx.x;
    if (idx >= 65536) return;
    int o = idx >> 8, i = idx & 255;
    ((float2*)g_WrzT)[i*256 + o] = make_float2(Whh[o*256 + i], Whh[(o+256)*256 + i]);
    g_WnT[i*256 + o] = Whh[(o+512)*256 + i];
    int pd = i*256 + ((o < 128) ? (2*o) : (2*(o-128) + 1));
    g_e1P [pd] = eW1[o*256 + i];
    g_e2mP[pd] = eW2[o*256 + i];
    g_e2sP[pd] = eW2[(o+256)*256 + i];
    g_oWH[0][pd] = __float2half_rn(oW1[o*256 + i]);
    g_oWH[1][pd] = __float2half_rn(oW2[o*256 + i]);
    g_oWH[2][pd] = __float2half_rn(oW3[o*256 + i]);
    g_oWH[3][pd] = __float2half_rn(oW4[o*256 + i]);
    if (idx < 6144) { int oo = idx / 8, ii = idx % 8; g_WihT[ii*768 + oo] = Wih[idx]; }
}

// ---------------- f32x2 helpers ----------------
__device__ __forceinline__ ull pack2(float a, float b){
    ull r; asm("mov.b64 %0, {%1, %2};" : "=l"(r) : "f"(a), "f"(b)); return r;
}
__device__ __forceinline__ void unpack2(ull v, float& a, float& b){
    asm("mov.b64 {%0, %1}, %2;" : "=f"(a), "=f"(b) : "l"(v));
}
__device__ __forceinline__ void fma2(ull& acc, ull a, ull b){
    asm("fma.rn.f32x2 %0, %1, %2, %0;" : "+l"(acc) : "l"(a), "l"(b));
}

__device__ __forceinline__ float selu_f(float x){
    const float sc = 1.0507009873554805f, al = 1.6732632423543772f;
    return x > 0.f ? sc*x : sc*(al*expm1f(x));
}
__device__ __forceinline__ float sigmoid_f(float x){ return 1.f/(1.f+expf(-x)); }

// Activation layout (8 rows x 256 cols, 2048 floats):
//   elem (r, c) at buf[(r>>2)*1024 + c*4 + (r&3)]
// Split-K matvec: thread (oc in [0,128), q in [0,8)) owns cols {oc, oc+128},
// all 8 rows, i in [q*32, q*32+32).

// fp32-weight version (encoder)
__device__ __noinline__ void smatvec8(const float* __restrict__ WT,
                                      const float* __restrict__ bias,
                                      const float* __restrict__ inT,
                                      float* __restrict__ outT,
                                      float* __restrict__ Pp,
                                      int oc, int q, int tid, int act)
{
    const float4* in4 = (const float4*)inT;
    const float2* w2p = (const float2*)WT + q*32*128 + oc;
    ull a00=0,a01=0,a02=0,a03=0;
    ull a10=0,a11=0,a12=0,a13=0;
#pragma unroll 8
    for (int ii = 0; ii < 32; ii++) {
        int i = q*32 + ii;
        float2 w = __ldg(w2p + ii*128);
        float4 u0 = in4[i];
        float4 u1 = in4[256 + i];
        ull p0 = pack2(u0.x,u0.y), p1 = pack2(u0.z,u0.w);
        ull p2 = pack2(u1.x,u1.y), p3 = pack2(u1.z,u1.w);
        ull wx = pack2(w.x,w.x), wy = pack2(w.y,w.y);
        fma2(a00,p0,wx); fma2(a01,p1,wx); fma2(a02,p2,wx); fma2(a03,p3,wx);
        fma2(a10,p0,wy); fma2(a11,p1,wy); fma2(a12,p2,wy); fma2(a13,p3,wy);
    }
    float* P = Pp + q*2048;
    float f0,f1,f2,f3;
    unpack2(a00,f0,f1); unpack2(a01,f2,f3); *(float4*)(P + oc*4)        = make_float4(f0,f1,f2,f3);
    unpack2(a10,f0,f1); unpack2(a11,f2,f3); *(float4*)(P + 512 + oc*4)  = make_float4(f0,f1,f2,f3);
    unpack2(a02,f0,f1); unpack2(a03,f2,f3); *(float4*)(P + 1024 + oc*4) = make_float4(f0,f1,f2,f3);
    unpack2(a12,f0,f1); unpack2(a13,f2,f3); *(float4*)(P + 1536 + oc*4) = make_float4(f0,f1,f2,f3);
    __syncthreads();
    const int e = tid*2;
    float vx = 0.f, vy = 0.f;
#pragma unroll
    for (int p = 0; p < 8; p++) {
        float2 s = *(float2*)(Pp + p*2048 + e);
        vx += s.x; vy += s.y;
    }
    float b = __ldg(bias + ((e & 1023) >> 2));
    vx += b; vy += b;
    if (act == 1) { vx = selu_f(vx); vy = selu_f(vy); }
    else if (act == 2) { vx = fmaxf(vx,0.f); vy = fmaxf(vy,0.f); }
    *(float2*)(outT + e) = make_float2(vx,vy);
    __syncthreads();
}

// fp16-weight version (ODE MLP)
__device__ __noinline__ void smatvec8h(const __half* __restrict__ WT,
                                       const float* __restrict__ bias,
                                       const float* __restrict__ inT,
                                       float* __restrict__ outT,
                                       float* __restrict__ Pp,
                                       int oc, int q, int tid, int act)
{
    const float4* in4 = (const float4*)inT;
    const __half2* w2p = (const __half2*)WT + q*32*128 + oc;
    ull a00=0,a01=0,a02=0,a03=0;
    ull a10=0,a11=0,a12=0,a13=0;
#pragma unroll 8
    for (int ii = 0; ii < 32; ii++) {
        int i = q*32 + ii;
        float2 w = __half22float2(__ldg(w2p + ii*128));
        float4 u0 = in4[i];
        float4 u1 = in4[256 + i];
        ull p0 = pack2(u0.x,u0.y), p1 = pack2(u0.z,u0.w);
        ull p2 = pack2(u1.x,u1.y), p3 = pack2(u1.z,u1.w);
        ull wx = pack2(w.x,w.x), wy = pack2(w.y,w.y);
        fma2(a00,p0,wx); fma2(a01,p1,wx); fma2(a02,p2,wx); fma2(a03,p3,wx);
        fma2(a10,p0,wy); fma2(a11,p1,wy); fma2(a12,p2,wy); fma2(a13,p3,wy);
    }
    float* P = Pp + q*2048;
    float f0,f1,f2,f3;
    unpack2(a00,f0,f1); unpack2(a01,f2,f3); *(float4*)(P + oc*4)        = make_float4(f0,f1,f2,f3);
    unpack2(a10,f0,f1); unpack2(a11,f2,f3); *(float4*)(P + 512 + oc*4)  = make_float4(f0,f1,f2,f3);
    unpack2(a02,f0,f1); unpack2(a03,f2,f3); *(float4*)(P + 1024 + oc*4) = make_float4(f0,f1,f2,f3);
    unpack2(a12,f0,f1); unpack2(a13,f2,f3); *(float4*)(P + 1536 + oc*4) = make_float4(f0,f1,f2,f3);
    __syncthreads();
    const int e = tid*2;
    float vx = 0.f, vy = 0.f;
#pragma unroll
    for (int p = 0; p < 8; p++) {
        float2 s = *(float2*)(Pp + p*2048 + e);
        vx += s.x; vy += s.y;
    }
    float b = __ldg(bias + ((e & 1023) >> 2));
    vx += b; vy += b;
    if (act == 1) { vx = selu_f(vx); vy = selu_f(vy); }
    *(float2*)(outT + e) = make_float2(vx,vy);
    __syncthreads();
}

__device__ __noinline__ void feval(const float* __restrict__ inT, float* __restrict__ outT,
                                   float* __restrict__ aT, float* __restrict__ bT,
                                   float* __restrict__ Pp,
                                   const float* ob1, const float* ob2,
                                   const float* ob3, const float* ob4,
                                   int oc, int q, int tid)
{
    smatvec8h(g_oWH[0], ob1, inT, aT, Pp, oc, q, tid, 1);
    smatvec8h(g_oWH[1], ob2, aT,  bT, Pp, oc, q, tid, 1);
    smatvec8h(g_oWH[2], ob3, bT,  aT, Pp, oc, q, tid, 1);
    smatvec8h(g_oWH[3], ob4, aT, outT, Pp, oc, q, tid, 0);
}

// ---------------- main persistent kernel ----------------
__global__ __launch_bounds__(NTH, 1)
void node_kernel(const float* __restrict__ x,     const float* __restrict__ meta,
                 const float* __restrict__ eps,   const float* __restrict__ times,
                 const float* __restrict__ doses,
                 const float* __restrict__ gbih,  const float* __restrict__ gbhh,
                 const float* __restrict__ eb1,   const float* __restrict__ eb2,
                 const float* __restrict__ ob1,   const float* __restrict__ ob2,
                 const float* __restrict__ ob3,   const float* __restrict__ ob4,
                 const float* __restrict__ fcW,   const float* __restrict__ fcb,
                 float* __restrict__ out)
{
    extern __shared__ float sm[];
    float* yT   = sm + 0*2048;
    float* tmpT = sm + 1*2048;   // stage input / k7
    float* aT   = sm + 2*2048;   // scratch; also "red" + encoder mean
    float* bT   = sm + 3*2048;
    float* y5T  = sm + 4*2048;   // also encoder std
    float* k1T  = sm + 5*2048;   // x cache during GRU
    float* k2T  = sm + 6*2048;
    float* k3T  = sm + 7*2048;
    float* k4T  = sm + 8*2048;
    float* k5T  = sm + 9*2048;
    float* k6T  = sm +10*2048;
    float* Pp   = sm +11*2048;   // 8*2048 split-K partials; GRU gate planes
    float* red  = aT;
    float* xc   = k1T;

    __shared__ float t_s[8], t1_s[8], dt_s[8], d_s[8], ds_s[8], meta_s[32];
    __shared__ int   act_s[8], accfl[8];

    const int tid  = threadIdx.x;
    const int oc   = tid & 127;      // ODE: column pair {oc, oc+128}
    const int q    = tid >> 7;       // ODE: K-chunk 0..7
    const int ht   = tid & 511;      // GRU half-local index
    const int h    = tid >> 9;       // GRU row half
    const int o    = ht & 255;       // GRU column
    const int qg   = ht >> 8;        // GRU: 0 -> r,z ; 1 -> n
    const int wid  = tid >> 5;
    const int lane = tid & 31;
    const int r0   = blockIdx.x * RPB;
    const int e2i  = tid*2;
    const int re0  = ((e2i >> 10) << 2) | (e2i & 3);

    for (int e = tid; e < 2048; e += NTH) { xc[e] = x[r0*256 + e]; yT[e] = 0.f; }
    if (tid < 32) meta_s[tid] = meta[r0*4 + tid];

    float wA[8], wB[8];
    float bA, bB, bN = 0.f;
    if (qg == 0) {
#pragma unroll
        for (int c = 0; c < 8; c++) { wA[c] = g_WihT[c*768 + o]; wB[c] = g_WihT[c*768 + o + 256]; }
        bA = gbih[o] + gbhh[o];
        bB = gbih[o+256] + gbhh[o+256];
    } else {
#pragma unroll
        for (int c = 0; c < 8; c++) { wA[c] = g_WihT[c*768 + o + 512]; wB[c] = 0.f; }
        bA = gbhh[o + 512];
        bN = gbih[o + 512];
        bB = 0.f;
    }
    __syncthreads();

    // ---------------- Phase A: GRU over 64 timesteps ----------------
    for (int t = 0; t < 64; t++) {
        if (qg == 0) {
            ull ar0 = pack2(bA,bA), ar1 = ar0, az0 = pack2(bB,bB), az1 = az0;
            const float2* wrz = (const float2*)g_WrzT + o;
            const float4* h4 = (const float4*)(yT + h*1024);
#pragma unroll 8
            for (int i = 0; i < 256; i++) {
                float2 w = __ldg(wrz + i*256);
                float4 u = h4[i];
                ull u01 = pack2(u.x,u.y), u23 = pack2(u.z,u.w);
                ull wx = pack2(w.x,w.x), wy = pack2(w.y,w.y);
                fma2(ar0,u01,wx); fma2(ar1,u23,wx);
                fma2(az0,u01,wy); fma2(az1,u23,wy);
            }
            float fr[4], fz[4];
            unpack2(ar0,fr[0],fr[1]); unpack2(ar1,fr[2],fr[3]);
            unpack2(az0,fz[0],fz[1]); unpack2(az1,fz[2],fz[3]);
#pragma unroll
            for (int k = 0; k < 4; k++) {
                int r = 4*h + k;
                float sr = 0.f, sz = 0.f;
#pragma unroll
                for (int c = 0; c < 4; c++) {
                    float xv = xc[r*256 + t*4 + c];
                    sr = fmaf(xv, wA[c], sr); sz = fmaf(xv, wB[c], sz);
                }
#pragma unroll
                for (int c = 0; c < 4; c++) {
                    float mv = meta_s[r*4 + c];
                    sr = fmaf(mv, wA[4+c], sr); sz = fmaf(mv, wB[4+c], sz);
                }
                fr[k] = sigmoid_f(fr[k] + sr);
                fz[k] = sigmoid_f(fz[k] + sz);
            }
            *(float4*)(Pp + h*2048 + o*4)        = make_float4(fr[0],fr[1],fr[2],fr[3]);
            *(float4*)(Pp + h*2048 + 1024 + o*4) = make_float4(fz[0],fz[1],fz[2],fz[3]);
            __syncthreads();
            __syncthreads();
        } else {
            ull an0 = pack2(bA,bA), an1 = an0;
            const float* wn = g_WnT + o;
            const float4* h4 = (const float4*)(yT + h*1024);
#pragma unroll 8
            for (int i = 0; i < 256; i++) {
                float w = __ldg(wn + i*256);
                float4 u = h4[i];
                ull w2 = pack2(w,w);
                fma2(an0, pack2(u.x,u.y), w2);
                fma2(an1, pack2(u.z,u.w), w2);
            }
            float hn[4];
            unpack2(an0,hn[0],hn[1]); unpack2(an1,hn[2],hn[3]);
            float inn[4];
#pragma unroll
            for (int k = 0; k < 4; k++) {
                int r = 4*h + k;
                float s = bN;
#pragma unroll
                for (int c = 0; c < 4; c++) s = fmaf(xc[r*256 + t*4 + c], wA[c], s);
#pragma unroll
                for (int c = 0; c < 4; c++) s = fmaf(meta_s[r*4 + c], wA[4+c], s);
                inn[k] = s;
            }
            __syncthreads();
            float4 R  = *(float4*)(Pp + h*2048 + o*4);
            float4 Z  = *(float4*)(Pp + h*2048 + 1024 + o*4);
            float4 ho = *(float4*)(yT + h*1024 + o*4);
            float Rr[4] = {R.x,R.y,R.z,R.w};
            float Zr[4] = {Z.x,Z.y,Z.z,Z.w};
            float hr[4] = {ho.x,ho.y,ho.z,ho.w};
            float hnew[4];
#pragma unroll
            for (int k = 0; k < 4; k++) {
                float n = tanhf(inn[k] + Rr[k]*hn[k]);
                hnew[k] = (1.f - Zr[k])*n + Zr[k]*hr[k];
            }
            *(float4*)(yT + h*1024 + o*4) = make_float4(hnew[0],hnew[1],hnew[2],hnew[3]);
            __syncthreads();
        }
    }

    // ---------------- Phase B: encoder -> y0 ----------------
    smatvec8(g_e1P,  eb1,       yT, bT,  Pp, oc, q, tid, 2);  // relu
    smatvec8(g_e2mP, eb2,       bT, aT,  Pp, oc, q, tid, 0);  // mean
    smatvec8(g_e2sP, eb2 + 256, bT, y5T, Pp, oc, q, tid, 0);  // std
    {
        int c = (e2i & 1023) >> 2;
        float m0 = aT[e2i], m1 = aT[e2i+1];
        float s0 = y5T[e2i], s1 = y5T[e2i+1];
        float ev0 = __ldg(eps + (r0 + re0)*256 + c);
        float ev1 = __ldg(eps + (r0 + re0 + 1)*256 + c);
        yT[e2i]   = fmaf(ev0, s0, m0);
        yT[e2i+1] = fmaf(ev1, s1, m1);
    }
    __syncthreads();

    // ---------------- Phase C: 4 x dopri5 (with FSAL) ----------------
    const float A21 = 0.2f;
    const float A31 = (float)(3.0/40.0),  A32 = (float)(9.0/40.0);
    const float A41 = (float)(44.0/45.0), A42 = (float)(-56.0/15.0), A43 = (float)(32.0/9.0);
    const float A51 = (float)(19372.0/6561.0), A52 = (float)(-25360.0/2187.0),
                A53 = (float)(64448.0/6561.0), A54 = (float)(-212.0/729.0);
    const float A61 = (float)(9017.0/3168.0), A62 = (float)(-355.0/33.0),
                A63 = (float)(46732.0/5247.0), A64 = (float)(49.0/176.0),
                A65 = (float)(-5103.0/18656.0);
    const float BC0 = (float)(35.0/384.0), BC2 = (float)(500.0/1113.0),
                BC3 = (float)(125.0/192.0), BC4 = (float)(-2187.0/6784.0),
                BC5 = (float)(11.0/84.0);
    const float EC0 = (float)(35.0/384.0 - 5179.0/57600.0);
    const float EC2 = (float)(500.0/1113.0 - 7571.0/16695.0);
    const float EC3 = (float)(125.0/192.0 - 393.0/640.0);
    const float EC4 = (float)(-2187.0/6784.0 + 92097.0/339200.0);
    const float EC5 = (float)(11.0/84.0 - 187.0/2100.0);
    const float EC6 = (float)(-1.0/40.0);

    for (int j = 0; j < 4; j++) {
        if (tid < 8) {
            int row = r0 + tid;
            float t0v = times[(j*1024 + row)*2 + 0];
            float t1v = times[(j*1024 + row)*2 + 1];
            t_s[tid]  = t0v;
            t1_s[tid] = t1v;
            dt_s[tid] = fmaxf(t1v - t0v, 1e-6f) * 0.1f;
            ds_s[tid] = (t0v < t1v) ? doses[j*1024 + row] : 0.f;
        }
        __syncthreads();
        {
            float2 y = *(float2*)(yT + e2i);
            y.x += ds_s[re0]; y.y += ds_s[re0 + 1];
            *(float2*)(yT + e2i) = y;
        }

        int fsal = 0;   // k7 of previous step valid in tmpT?
        for (int step = 0; step < 32; step++) {
            int myact = 0;
            if (tid < 8) {
                float tt = t_s[tid], t1v = t1_s[tid];
                myact = (tt < t1v) ? 1 : 0;
                act_s[tid] = myact;
                float rem = fmaxf(t1v - tt, 0.f);
                d_s[tid] = fminf(fmaxf(dt_s[tid], 0.f), rem);
            }
            if (!__syncthreads_or(myact)) break;   // uniform exit

            const float d0 = d_s[re0], d1 = d_s[re0 + 1];

#define COMB2(DST, EX, EY) do { \
            float2 _y = *(float2*)(yT + e2i); \
            float2 _t; \
            _t.x = fmaf(d0, (EX), _y.x); _t.y = fmaf(d1, (EY), _y.y); \
            *(float2*)(DST + e2i) = _t; } while(0)

            if (fsal) {
                // FSAL: k1 = accepted ? k7(prev, in tmpT) : k1(prev). Exact.
                float2 kp = *(float2*)(k1T + e2i);
                float2 k7 = *(float2*)(tmpT + e2i);
                if (accfl[re0])     kp.x = k7.x;
                if (accfl[re0 + 1]) kp.y = k7.y;
                *(float2*)(k1T + e2i) = kp;
            } else {
                feval(yT, k1T, aT, bT, Pp, ob1, ob2, ob3, ob4, oc, q, tid);
            }
            {
                float2 a = *(float2*)(k1T + e2i);
                COMB2(tmpT, A21*a.x, A21*a.y);
            }
            __syncthreads();
            feval(tmpT, k2T, aT, bT, Pp, ob1, ob2, ob3, ob4, oc, q, tid);
            {
                float2 a = *(float2*)(k1T + e2i); float2 b = *(float2*)(k2T + e2i);
                COMB2(tmpT, A31*a.x + A32*b.x, A31*a.y + A32*b.y);
            }
            __syncthreads();
            feval(tmpT, k3T, aT, bT, Pp, ob1, ob2, ob3, ob4, oc, q, tid);
            {
                float2 a = *(float2*)(k1T + e2i); float2 b = *(float2*)(k2T + e2i);
                float2 c = *(float2*)(k3T + e2i);
                COMB2(tmpT, A41*a.x + A42*b.x + A43*c.x,
                            A41*a.y + A42*b.y + A43*c.y);
            }
            __syncthreads();
            feval(tmpT, k4T, aT, bT, Pp, ob1, ob2, ob3, ob4, oc, q, tid);
            {
                float2 a = *(float2*)(k1T + e2i); float2 b = *(float2*)(k2T + e2i);
                float2 c = *(float2*)(k3T + e2i); float2 e = *(float2*)(k4T + e2i);
                COMB2(tmpT, A51*a.x + A52*b.x + A53*c.x + A54*e.x,
                            A51*a.y + A52*b.y + A53*c.y + A54*e.y);
            }
            __syncthreads();
            feval(tmpT, k5T, aT, bT, Pp, ob1, ob2, ob3, ob4, oc, q, tid);
            {
                float2 a = *(float2*)(k1T + e2i); float2 b = *(float2*)(k2T + e2i);
                float2 c = *(float2*)(k3T + e2i); float2 e = *(float2*)(k4T + e2i);
                float2 f = *(float2*)(k5T + e2i);
                COMB2(tmpT, A61*a.x + A62*b.x + A63*c.x + A64*e.x + A65*f.x,
                            A61*a.y + A62*b.y + A63*c.y + A64*e.y + A65*f.y);
            }
            __syncthreads();
            feval(tmpT, k6T, aT, bT, Pp, ob1, ob2, ob3, ob4, oc, q, tid);
            {
                float2 a = *(float2*)(k1T + e2i); float2 c = *(float2*)(k3T + e2i);
                float2 e = *(float2*)(k4T + e2i); float2 f = *(float2*)(k5T + e2i);
                float2 g6 = *(float2*)(k6T + e2i);
                COMB2(y5T, BC0*a.x + BC2*c.x + BC3*e.x + BC4*f.x + BC5*g6.x,
                           BC0*a.y + BC2*c.y + BC3*e.y + BC4*f.y + BC5*g6.y);
            }
            __syncthreads();
            feval(y5T, tmpT, aT, bT, Pp, ob1, ob2, ob3, ob4, oc, q, tid);   // k7 -> tmpT

            {
                float2 a = *(float2*)(k1T + e2i); float2 c = *(float2*)(k3T + e2i);
                float2 e = *(float2*)(k4T + e2i); float2 f = *(float2*)(k5T + e2i);
                float2 g6 = *(float2*)(k6T + e2i); float2 s7 = *(float2*)(tmpT + e2i);
                float2 y = *(float2*)(yT + e2i);  float2 y5 = *(float2*)(y5T + e2i);
                float ex = EC0*a.x + EC2*c.x + EC3*e.x + EC4*f.x + EC5*g6.x + EC6*s7.x;
                float ey = EC0*a.y + EC2*c.y + EC3*e.y + EC4*f.y + EC5*g6.y + EC6*s7.y;
                float qx = d0*ex / (1e-6f + 1e-3f*fmaxf(fabsf(y.x), fabsf(y5.x)));
                float qy = d1*ey / (1e-6f + 1e-3f*fmaxf(fabsf(y.y), fabsf(y5.y)));
                *(float2*)(red + e2i) = make_float2(qx*qx, qy*qy);
            }
            __syncthreads();
            if (wid < 8) {
                int r = wid;
                const float* rp = red + ((r>>2)<<10) + (r&3);
                float s = 0.f;
#pragma unroll
                for (int c = 0; c < 8; c++) s += rp[(lane + 32*c)*4];
                s += __shfl_xor_sync(0xffffffffu, s, 16);
                s += __shfl_xor_sync(0xffffffffu, s, 8);
                s += __shfl_xor_sync(0xffffffffu, s, 4);
                s += __shfl_xor_sync(0xffffffffu, s, 2);
                s += __shfl_xor_sync(0xffffffffu, s, 1);
                if (lane == 0) {
                    float en = sqrtf(s * (1.f/256.f));
                    int active = act_s[r];
                    int acc = (en <= 1.f) && active;
                    accfl[r] = acc;
                    float dtc = d_s[r];
                    if (acc) t_s[r] += dtc;
                    if (active) {
                        float fac = 0.9f * powf(en + 1e-10f, -0.2f);
                        fac = fminf(fmaxf(fac, 0.2f), 10.f);
                        dt_s[r] = fmaxf(dtc, 1e-8f) * fac;
                    }
                }
            }
            __syncthreads();
            {
                float2 y = *(float2*)(yT + e2i);
                float2 y5 = *(float2*)(y5T + e2i);
                if (accfl[re0])     y.x = y5.x;
                if (accfl[re0 + 1]) y.y = y5.y;
                *(float2*)(yT + e2i) = y;
            }
            __syncthreads();
            fsal = 1;   // tmpT holds k7 = f(y5); accfl selects per row
#undef COMB2
        }
    }

    // ---------------- Phase D: linear head ----------------
    {
        float fcw = __ldg(fcW + ((e2i & 1023) >> 2));
        float2 y = *(float2*)(yT + e2i);
        *(float2*)(red + e2i) = make_float2(y.x*fcw, y.y*fcw);
        __syncthreads();
        if (wid < 8) {
            int r = wid;
            const float* rp = red + ((r>>2)<<10) + (r&3);
            float s = 0.f;
#pragma unroll
            for (int c = 0; c < 8; c++) s += rp[(lane + 32*c)*4];
            s += __shfl_xor_sync(0xffffffffu, s, 16);
            s += __shfl_xor_sync(0xffffffffu, s, 8);
            s += __shfl_xor_sync(0xffffffffu, s, 4);
            s += __shfl_xor_sync(0xffffffffu, s, 2);
            s += __shfl_xor_sync(0xffffffffu, s, 1);
            if (lane == 0) {
                s += fcb[0];
#pragma unroll
                for (int c = 0; c < 4; c++) s += meta_s[r*4 + c] * fcW[256 + c];
                out[r0 + r] = s;
            }
        }
    }
}

extern "C" void kernel_launch(void* const* d_in, const int* in_sizes, int n_in,
                              void* d_out, int out_size)
{
    const float* x     = (const float*)d_in[0];
    const float* meta  = (const float*)d_in[1];
    const float* eps   = (const float*)d_in[2];
    const float* times = (const float*)d_in[3];
    const float* doses = (const float*)d_in[4];
    const float* gWih  = (const float*)d_in[5];
    const float* gWhh  = (const float*)d_in[6];
    const float* gbih  = (const float*)d_in[7];
    const float* gbhh  = (const float*)d_in[8];
    const float* eW1   = (const float*)d_in[9];
    const float* eb1   = (const float*)d_in[10];
    const float* eW2   = (const float*)d_in[11];
    const float* eb2   = (const float*)d_in[12];
    const float* oW1   = (const float*)d_in[13];
    const float* ob1   = (const float*)d_in[14];
    const float* oW2   = (const float*)d_in[15];
    const float* ob2   = (const float*)d_in[16];
    const float* oW3   = (const float*)d_in[17];
    const float* ob3   = (const float*)d_in[18];
    const float* oW4   = (const float*)d_in[19];
    const float* ob4   = (const float*)d_in[20];
    const float* fcW   = (const float*)d_in[21];
    const float* fcb   = (const float*)d_in[22];
    float* out = (float*)d_out;

    prep_kernel<<<256, 256>>>(gWih, gWhh, eW1, eW2, oW1, oW2, oW3, oW4);

    const int smem_bytes = (11*2048 + 8*2048) * sizeof(float);   // 155648
    static int attr_done = 0;
    if (!attr_done) {
        cudaFuncSetAttribute(node_kernel, cudaFuncAttributeMaxDynamicSharedMemorySize, smem_bytes);
        attr_done = 1;
    }
    node_kernel<<<128, NTH, smem_bytes>>>(x, meta, eps, times, doses,
                                          gbih, gbhh, eb1, eb2,
                                          ob1, ob2, ob3, ob4, fcW, fcb, out);
}

// round 10
// speedup vs baseline: 1.6667x; 1.0443x over previous
#include <cuda_runtime.h>
#include <cuda_fp16.h>
#include <math.h>

#define NTH 1024
#define RPB 8

typedef unsigned long long ull;

// ---------------- transposed/packed weight scratch (device globals) ----
// Packed 256x256 layout "P": pair slot pc in [0,128): (col pc, col pc+128)
//   dst[i*256 + 2*pc + 0] = W[pc][i] ; dst[i*256 + 2*pc + 1] = W[pc+128][i]
__device__ float  g_WrzT[2*256*256];   // float2 [i*256+o] = (Wr[o][i], Wz[o][i])
__device__ float  g_WnT [256*256];     // [i*256+o]
__device__ float  g_WihT[8*768];       // [ii*768+o]
__device__ float  g_e1P [256*256];
__device__ float  g_e2mP[256*256];
__device__ float  g_e2sP[256*256];
__device__ __half g_oWH [4][256*256];  // ODE weights fp16, "P" packing

__global__ void prep_kernel(const float* __restrict__ Wih, const float* __restrict__ Whh,
                            const float* __restrict__ eW1, const float* __restrict__ eW2,
                            const float* __restrict__ oW1, const float* __restrict__ oW2,
                            const float* __restrict__ oW3, const float* __restrict__ oW4)
{
    int idx = blockIdx.x*blockDim.x + threadIdx.x;
    if (idx >= 65536) return;
    int o = idx >> 8, i = idx & 255;
    ((float2*)g_WrzT)[i*256 + o] = make_float2(Whh[o*256 + i], Whh[(o+256)*256 + i]);
    g_WnT[i*256 + o] = Whh[(o+512)*256 + i];
    int pd = i*256 + ((o < 128) ? (2*o) : (2*(o-128) + 1));
    g_e1P [pd] = eW1[o*256 + i];
    g_e2mP[pd] = eW2[o*256 + i];
    g_e2sP[pd] = eW2[(o+256)*256 + i];
    g_oWH[0][pd] = __float2half_rn(oW1[o*256 + i]);
    g_oWH[1][pd] = __float2half_rn(oW2[o*256 + i]);
    g_oWH[2][pd] = __float2half_rn(oW3[o*256 + i]);
    g_oWH[3][pd] = __float2half_rn(oW4[o*256 + i]);
    if (idx < 6144) { int oo = idx / 8, ii = idx % 8; g_WihT[ii*768 + oo] = Wih[idx]; }
}

// ---------------- f32x2 helpers ----------------
__device__ __forceinline__ ull pack2(float a, float b){
    ull r; asm("mov.b64 %0, {%1, %2};" : "=l"(r) : "f"(a), "f"(b)); return r;
}
__device__ __forceinline__ void unpack2(ull v, float& a, float& b){
    asm("mov.b64 {%0, %1}, %2;" : "=f"(a), "=f"(b) : "l"(v));
}
__device__ __forceinline__ void fma2(ull& acc, ull a, ull b){
    asm("fma.rn.f32x2 %0, %1, %2, %0;" : "+l"(acc) : "l"(a), "l"(b));
}

// SELU without expm1f (libdevice slow path!): for x<=0,
// lambda*alpha*(e^x - 1) = fma(LA, __expf(x), -LA). 1 MUFU + 1 FMA.
__device__ __forceinline__ float selu_f(float x){
    const float sc = 1.0507009873554805f;
    const float la = 1.7580993408473766f;   // lambda*alpha
    return x > 0.f ? sc*x : fmaf(la, __expf(x), -la);
}
__device__ __forceinline__ float sigmoid_f(float x){
    return 1.f/(1.f + __expf(-x));
}

// Activation layout (8 rows x 256 cols, 2048 floats):
//   elem (r, c) at buf[(r>>2)*1024 + c*4 + (r&3)]
// Split-K matvec: thread (oc in [0,128), q in [0,8)) owns cols {oc, oc+128},
// all 8 rows, i in [q*32, q*32+32).

// fp32-weight version (encoder)
__device__ __noinline__ void smatvec8(const float* __restrict__ WT,
                                      const float* __restrict__ bias,
                                      const float* __restrict__ inT,
                                      float* __restrict__ outT,
                                      float* __restrict__ Pp,
                                      int oc, int q, int tid, int act)
{
    const float4* in4 = (const float4*)inT;
    const float2* w2p = (const float2*)WT + q*32*128 + oc;
    ull a00=0,a01=0,a02=0,a03=0;
    ull a10=0,a11=0,a12=0,a13=0;
#pragma unroll 8
    for (int ii = 0; ii < 32; ii++) {
        int i = q*32 + ii;
        float2 w = __ldg(w2p + ii*128);
        float4 u0 = in4[i];
        float4 u1 = in4[256 + i];
        ull p0 = pack2(u0.x,u0.y), p1 = pack2(u0.z,u0.w);
        ull p2 = pack2(u1.x,u1.y), p3 = pack2(u1.z,u1.w);
        ull wx = pack2(w.x,w.x), wy = pack2(w.y,w.y);
        fma2(a00,p0,wx); fma2(a01,p1,wx); fma2(a02,p2,wx); fma2(a03,p3,wx);
        fma2(a10,p0,wy); fma2(a11,p1,wy); fma2(a12,p2,wy); fma2(a13,p3,wy);
    }
    float* P = Pp + q*2048;
    float f0,f1,f2,f3;
    unpack2(a00,f0,f1); unpack2(a01,f2,f3); *(float4*)(P + oc*4)        = make_float4(f0,f1,f2,f3);
    unpack2(a10,f0,f1); unpack2(a11,f2,f3); *(float4*)(P + 512 + oc*4)  = make_float4(f0,f1,f2,f3);
    unpack2(a02,f0,f1); unpack2(a03,f2,f3); *(float4*)(P + 1024 + oc*4) = make_float4(f0,f1,f2,f3);
    unpack2(a12,f0,f1); unpack2(a13,f2,f3); *(float4*)(P + 1536 + oc*4) = make_float4(f0,f1,f2,f3);
    __syncthreads();
    const int e = tid*2;
    float vx = 0.f, vy = 0.f;
#pragma unroll
    for (int p = 0; p < 8; p++) {
        float2 s = *(float2*)(Pp + p*2048 + e);
        vx += s.x; vy += s.y;
    }
    float b = __ldg(bias + ((e & 1023) >> 2));
    vx += b; vy += b;
    if (act == 1) { vx = selu_f(vx); vy = selu_f(vy); }
    else if (act == 2) { vx = fmaxf(vx,0.f); vy = fmaxf(vy,0.f); }
    *(float2*)(outT + e) = make_float2(vx,vy);
    __syncthreads();
}

// fp16-weight version (ODE MLP)
__device__ __noinline__ void smatvec8h(const __half* __restrict__ WT,
                                       const float* __restrict__ bias,
                                       const float* __restrict__ inT,
                                       float* __restrict__ outT,
                                       float* __restrict__ Pp,
                                       int oc, int q, int tid, int act)
{
    const float4* in4 = (const float4*)inT;
    const __half2* w2p = (const __half2*)WT + q*32*128 + oc;
    ull a00=0,a01=0,a02=0,a03=0;
    ull a10=0,a11=0,a12=0,a13=0;
#pragma unroll 8
    for (int ii = 0; ii < 32; ii++) {
        int i = q*32 + ii;
        float2 w = __half22float2(__ldg(w2p + ii*128));
        float4 u0 = in4[i];
        float4 u1 = in4[256 + i];
        ull p0 = pack2(u0.x,u0.y), p1 = pack2(u0.z,u0.w);
        ull p2 = pack2(u1.x,u1.y), p3 = pack2(u1.z,u1.w);
        ull wx = pack2(w.x,w.x), wy = pack2(w.y,w.y);
        fma2(a00,p0,wx); fma2(a01,p1,wx); fma2(a02,p2,wx); fma2(a03,p3,wx);
        fma2(a10,p0,wy); fma2(a11,p1,wy); fma2(a12,p2,wy); fma2(a13,p3,wy);
    }
    float* P = Pp + q*2048;
    float f0,f1,f2,f3;
    unpack2(a00,f0,f1); unpack2(a01,f2,f3); *(float4*)(P + oc*4)        = make_float4(f0,f1,f2,f3);
    unpack2(a10,f0,f1); unpack2(a11,f2,f3); *(float4*)(P + 512 + oc*4)  = make_float4(f0,f1,f2,f3);
    unpack2(a02,f0,f1); unpack2(a03,f2,f3); *(float4*)(P + 1024 + oc*4) = make_float4(f0,f1,f2,f3);
    unpack2(a12,f0,f1); unpack2(a13,f2,f3); *(float4*)(P + 1536 + oc*4) = make_float4(f0,f1,f2,f3);
    __syncthreads();
    const int e = tid*2;
    float vx = 0.f, vy = 0.f;
#pragma unroll
    for (int p = 0; p < 8; p++) {
        float2 s = *(float2*)(Pp + p*2048 + e);
        vx += s.x; vy += s.y;
    }
    float b = __ldg(bias + ((e & 1023) >> 2));
    vx += b; vy += b;
    if (act == 1) { vx = selu_f(vx); vy = selu_f(vy); }
    *(float2*)(outT + e) = make_float2(vx,vy);
    __syncthreads();
}

__device__ __noinline__ void feval(const float* __restrict__ inT, float* __restrict__ outT,
                                   float* __restrict__ aT, float* __restrict__ bT,
                                   float* __restrict__ Pp,
                                   const float* ob1, const float* ob2,
                                   const float* ob3, const float* ob4,
                                   int oc, int q, int tid)
{
    smatvec8h(g_oWH[0], ob1, inT, aT, Pp, oc, q, tid, 1);
    smatvec8h(g_oWH[1], ob2, aT,  bT, Pp, oc, q, tid, 1);
    smatvec8h(g_oWH[2], ob3, bT,  aT, Pp, oc, q, tid, 1);
    smatvec8h(g_oWH[3], ob4, aT, outT, Pp, oc, q, tid, 0);
}

// ---------------- main persistent kernel ----------------
__global__ __launch_bounds__(NTH, 1)
void node_kernel(const float* __restrict__ x,     const float* __restrict__ meta,
                 const float* __restrict__ eps,   const float* __restrict__ times,
                 const float* __restrict__ doses,
                 const float* __restrict__ gbih,  const float* __restrict__ gbhh,
                 const float* __restrict__ eb1,   const float* __restrict__ eb2,
                 const float* __restrict__ ob1,   const float* __restrict__ ob2,
                 const float* __restrict__ ob3,   const float* __restrict__ ob4,
                 const float* __restrict__ fcW,   const float* __restrict__ fcb,
                 float* __restrict__ out)
{
    extern __shared__ float sm[];
    float* yT   = sm + 0*2048;
    float* tmpT = sm + 1*2048;   // stage input / k7
    float* aT   = sm + 2*2048;   // scratch; also "red" + encoder mean
    float* bT   = sm + 3*2048;
    float* y5T  = sm + 4*2048;   // also encoder std
    float* k1T  = sm + 5*2048;   // x cache during GRU
    float* k2T  = sm + 6*2048;
    float* k3T  = sm + 7*2048;
    float* k4T  = sm + 8*2048;
    float* k5T  = sm + 9*2048;
    float* k6T  = sm +10*2048;
    float* Pp   = sm +11*2048;   // 8*2048 split-K partials; GRU gate planes
    float* red  = aT;
    float* xc   = k1T;

    __shared__ float t_s[8], t1_s[8], dt_s[8], d_s[8], ds_s[8], meta_s[32];
    __shared__ int   act_s[8], accfl[8];

    const int tid  = threadIdx.x;
    const int oc   = tid & 127;      // ODE: column pair {oc, oc+128}
    const int q    = tid >> 7;       // ODE: K-chunk 0..7
    const int ht   = tid & 511;      // GRU half-local index
    const int h    = tid >> 9;       // GRU row half
    const int o    = ht & 255;       // GRU column
    const int qg   = ht >> 8;        // GRU: 0 -> r,z ; 1 -> n
    const int wid  = tid >> 5;
    const int lane = tid & 31;
    const int r0   = blockIdx.x * RPB;
    const int e2i  = tid*2;
    const int re0  = ((e2i >> 10) << 2) | (e2i & 3);

    for (int e = tid; e < 2048; e += NTH) { xc[e] = x[r0*256 + e]; yT[e] = 0.f; }
    if (tid < 32) meta_s[tid] = meta[r0*4 + tid];

    float wA[8], wB[8];
    float bA, bB, bN = 0.f;
    if (qg == 0) {
#pragma unroll
        for (int c = 0; c < 8; c++) { wA[c] = g_WihT[c*768 + o]; wB[c] = g_WihT[c*768 + o + 256]; }
        bA = gbih[o] + gbhh[o];
        bB = gbih[o+256] + gbhh[o+256];
    } else {
#pragma unroll
        for (int c = 0; c < 8; c++) { wA[c] = g_WihT[c*768 + o + 512]; wB[c] = 0.f; }
        bA = gbhh[o + 512];
        bN = gbih[o + 512];
        bB = 0.f;
    }
    __syncthreads();

    // ---------------- Phase A: GRU over 64 timesteps ----------------
    for (int t = 0; t < 64; t++) {
        if (qg == 0) {
            ull ar0 = pack2(bA,bA), ar1 = ar0, az0 = pack2(bB,bB), az1 = az0;
            const float2* wrz = (const float2*)g_WrzT + o;
            const float4* h4 = (const float4*)(yT + h*1024);
#pragma unroll 8
            for (int i = 0; i < 256; i++) {
                float2 w = __ldg(wrz + i*256);
                float4 u = h4[i];
                ull u01 = pack2(u.x,u.y), u23 = pack2(u.z,u.w);
                ull wx = pack2(w.x,w.x), wy = pack2(w.y,w.y);
                fma2(ar0,u01,wx); fma2(ar1,u23,wx);
                fma2(az0,u01,wy); fma2(az1,u23,wy);
            }
            float fr[4], fz[4];
            unpack2(ar0,fr[0],fr[1]); unpack2(ar1,fr[2],fr[3]);
            unpack2(az0,fz[0],fz[1]); unpack2(az1,fz[2],fz[3]);
#pragma unroll
            for (int k = 0; k < 4; k++) {
                int r = 4*h + k;
                float sr = 0.f, sz = 0.f;
#pragma unroll
                for (int c = 0; c < 4; c++) {
                    float xv = xc[r*256 + t*4 + c];
                    sr = fmaf(xv, wA[c], sr); sz = fmaf(xv, wB[c], sz);
                }
#pragma unroll
                for (int c = 0; c < 4; c++) {
                    float mv = meta_s[r*4 + c];
                    sr = fmaf(mv, wA[4+c], sr); sz = fmaf(mv, wB[4+c], sz);
                }
                fr[k] = sigmoid_f(fr[k] + sr);
                fz[k] = sigmoid_f(fz[k] + sz);
            }
            *(float4*)(Pp + h*2048 + o*4)        = make_float4(fr[0],fr[1],fr[2],fr[3]);
            *(float4*)(Pp + h*2048 + 1024 + o*4) = make_float4(fz[0],fz[1],fz[2],fz[3]);
            __syncthreads();
            __syncthreads();
        } else {
            ull an0 = pack2(bA,bA), an1 = an0;
            const float* wn = g_WnT + o;
            const float4* h4 = (const float4*)(yT + h*1024);
#pragma unroll 8
            for (int i = 0; i < 256; i++) {
                float w = __ldg(wn + i*256);
                float4 u = h4[i];
                ull w2 = pack2(w,w);
                fma2(an0, pack2(u.x,u.y), w2);
                fma2(an1, pack2(u.z,u.w), w2);
            }
            float hn[4];
            unpack2(an0,hn[0],hn[1]); unpack2(an1,hn[2],hn[3]);
            float inn[4];
#pragma unroll
            for (int k = 0; k < 4; k++) {
                int r = 4*h + k;
                float s = bN;
#pragma unroll
                for (int c = 0; c < 4; c++) s = fmaf(xc[r*256 + t*4 + c], wA[c], s);
#pragma unroll
                for (int c = 0; c < 4; c++) s = fmaf(meta_s[r*4 + c], wA[4+c], s);
                inn[k] = s;
            }
            __syncthreads();
            float4 R  = *(float4*)(Pp + h*2048 + o*4);
            float4 Z  = *(float4*)(Pp + h*2048 + 1024 + o*4);
            float4 ho = *(float4*)(yT + h*1024 + o*4);
            float Rr[4] = {R.x,R.y,R.z,R.w};
            float Zr[4] = {Z.x,Z.y,Z.z,Z.w};
            float hr[4] = {ho.x,ho.y,ho.z,ho.w};
            float hnew[4];
#pragma unroll
            for (int k = 0; k < 4; k++) {
                float n = tanhf(inn[k] + Rr[k]*hn[k]);
                hnew[k] = (1.f - Zr[k])*n + Zr[k]*hr[k];
            }
            *(float4*)(yT + h*1024 + o*4) = make_float4(hnew[0],hnew[1],hnew[2],hnew[3]);
            __syncthreads();
        }
    }

    // ---------------- Phase B: encoder -> y0 ----------------
    smatvec8(g_e1P,  eb1,       yT, bT,  Pp, oc, q, tid, 2);  // relu
    smatvec8(g_e2mP, eb2,       bT, aT,  Pp, oc, q, tid, 0);  // mean
    smatvec8(g_e2sP, eb2 + 256, bT, y5T, Pp, oc, q, tid, 0);  // std
    {
        int c = (e2i & 1023) >> 2;
        float m0 = aT[e2i], m1 = aT[e2i+1];
        float s0 = y5T[e2i], s1 = y5T[e2i+1];
        float ev0 = __ldg(eps + (r0 + re0)*256 + c);
        float ev1 = __ldg(eps + (r0 + re0 + 1)*256 + c);
        yT[e2i]   = fmaf(ev0, s0, m0);
        yT[e2i+1] = fmaf(ev1, s1, m1);
    }
    __syncthreads();

    // ---------------- Phase C: 4 x dopri5 (with FSAL) ----------------
    const float A21 = 0.2f;
    const float A31 = (float)(3.0/40.0),  A32 = (float)(9.0/40.0);
    const float A41 = (float)(44.0/45.0), A42 = (float)(-56.0/15.0), A43 = (float)(32.0/9.0);
    const float A51 = (float)(19372.0/6561.0), A52 = (float)(-25360.0/2187.0),
                A53 = (float)(64448.0/6561.0), A54 = (float)(-212.0/729.0);
    const float A61 = (float)(9017.0/3168.0), A62 = (float)(-355.0/33.0),
                A63 = (float)(46732.0/5247.0), A64 = (float)(49.0/176.0),
                A65 = (float)(-5103.0/18656.0);
    const float BC0 = (float)(35.0/384.0), BC2 = (float)(500.0/1113.0),
                BC3 = (float)(125.0/192.0), BC4 = (float)(-2187.0/6784.0),
                BC5 = (float)(11.0/84.0);
    const float EC0 = (float)(35.0/384.0 - 5179.0/57600.0);
    const float EC2 = (float)(500.0/1113.0 - 7571.0/16695.0);
    const float EC3 = (float)(125.0/192.0 - 393.0/640.0);
    const float EC4 = (float)(-2187.0/6784.0 + 92097.0/339200.0);
    const float EC5 = (float)(11.0/84.0 - 187.0/2100.0);
    const float EC6 = (float)(-1.0/40.0);

    for (int j = 0; j < 4; j++) {
        if (tid < 8) {
            int row = r0 + tid;
            float t0v = times[(j*1024 + row)*2 + 0];
            float t1v = times[(j*1024 + row)*2 + 1];
            t_s[tid]  = t0v;
            t1_s[tid] = t1v;
            dt_s[tid] = fmaxf(t1v - t0v, 1e-6f) * 0.1f;
            ds_s[tid] = (t0v < t1v) ? doses[j*1024 + row] : 0.f;
        }
        __syncthreads();
        {
            float2 y = *(float2*)(yT + e2i);
            y.x += ds_s[re0]; y.y += ds_s[re0 + 1];
            *(float2*)(yT + e2i) = y;
        }

        int fsal = 0;   // k7 of previous step valid in tmpT?
        for (int step = 0; step < 32; step++) {
            int myact = 0;
            if (tid < 8) {
                float tt = t_s[tid], t1v = t1_s[tid];
                myact = (tt < t1v) ? 1 : 0;
                act_s[tid] = myact;
                float rem = fmaxf(t1v - tt, 0.f);
                d_s[tid] = fminf(fmaxf(dt_s[tid], 0.f), rem);
            }
            if (!__syncthreads_or(myact)) break;   // uniform exit

            const float d0 = d_s[re0], d1 = d_s[re0 + 1];

#define COMB2(DST, EX, EY) do { \
            float2 _y = *(float2*)(yT + e2i); \
            float2 _t; \
            _t.x = fmaf(d0, (EX), _y.x); _t.y = fmaf(d1, (EY), _y.y); \
            *(float2*)(DST + e2i) = _t; } while(0)

            if (fsal) {
                // FSAL: k1 = accepted ? k7(prev, in tmpT) : k1(prev). Exact.
                float2 kp = *(float2*)(k1T + e2i);
                float2 k7 = *(float2*)(tmpT + e2i);
                if (accfl[re0])     kp.x = k7.x;
                if (accfl[re0 + 1]) kp.y = k7.y;
                *(float2*)(k1T + e2i) = kp;
            } else {
                feval(yT, k1T, aT, bT, Pp, ob1, ob2, ob3, ob4, oc, q, tid);
            }
            {
                float2 a = *(float2*)(k1T + e2i);
                COMB2(tmpT, A21*a.x, A21*a.y);
            }
            __syncthreads();
            feval(tmpT, k2T, aT, bT, Pp, ob1, ob2, ob3, ob4, oc, q, tid);
            {
                float2 a = *(float2*)(k1T + e2i); float2 b = *(float2*)(k2T + e2i);
                COMB2(tmpT, A31*a.x + A32*b.x, A31*a.y + A32*b.y);
            }
            __syncthreads();
            feval(tmpT, k3T, aT, bT, Pp, ob1, ob2, ob3, ob4, oc, q, tid);
            {
                float2 a = *(float2*)(k1T + e2i); float2 b = *(float2*)(k2T + e2i);
                float2 c = *(float2*)(k3T + e2i);
                COMB2(tmpT, A41*a.x + A42*b.x + A43*c.x,
                            A41*a.y + A42*b.y + A43*c.y);
            }
            __syncthreads();
            feval(tmpT, k4T, aT, bT, Pp, ob1, ob2, ob3, ob4, oc, q, tid);
            {
                float2 a = *(float2*)(k1T + e2i); float2 b = *(float2*)(k2T + e2i);
                float2 c = *(float2*)(k3T + e2i); float2 e = *(float2*)(k4T + e2i);
                COMB2(tmpT, A51*a.x + A52*b.x + A53*c.x + A54*e.x,
                            A51*a.y + A52*b.y + A53*c.y + A54*e.y);
            }
            __syncthreads();
            feval(tmpT, k5T, aT, bT, Pp, ob1, ob2, ob3, ob4, oc, q, tid);
            {
                float2 a = *(float2*)(k1T + e2i); float2 b = *(float2*)(k2T + e2i);
                float2 c = *(float2*)(k3T + e2i); float2 e = *(float2*)(k4T + e2i);
                float2 f = *(float2*)(k5T + e2i);
                COMB2(tmpT, A61*a.x + A62*b.x + A63*c.x + A64*e.x + A65*f.x,
                            A61*a.y + A62*b.y + A63*c.y + A64*e.y + A65*f.y);
            }
            __syncthreads();
            feval(tmpT, k6T, aT, bT, Pp, ob1, ob2, ob3, ob4, oc, q, tid);
            {
                float2 a = *(float2*)(k1T + e2i); float2 c = *(float2*)(k3T + e2i);
                float2 e = *(float2*)(k4T + e2i); float2 f = *(float2*)(k5T + e2i);
                float2 g6 = *(float2*)(k6T + e2i);
                COMB2(y5T, BC0*a.x + BC2*c.x + BC3*e.x + BC4*f.x + BC5*g6.x,
                           BC0*a.y + BC2*c.y + BC3*e.y + BC4*f.y + BC5*g6.y);
            }
            __syncthreads();
            feval(y5T, tmpT, aT, bT, Pp, ob1, ob2, ob3, ob4, oc, q, tid);   // k7 -> tmpT

            {
                float2 a = *(float2*)(k1T + e2i); float2 c = *(float2*)(k3T + e2i);
                float2 e = *(float2*)(k4T + e2i); float2 f = *(float2*)(k5T + e2i);
                float2 g6 = *(float2*)(k6T + e2i); float2 s7 = *(float2*)(tmpT + e2i);
                float2 y = *(float2*)(yT + e2i);  float2 y5 = *(float2*)(y5T + e2i);
                float ex = EC0*a.x + EC2*c.x + EC3*e.x + EC4*f.x + EC5*g6.x + EC6*s7.x;
                float ey = EC0*a.y + EC2*c.y + EC3*e.y + EC4*f.y + EC5*g6.y + EC6*s7.y;
                float qx = d0*ex / (1e-6f + 1e-3f*fmaxf(fabsf(y.x), fabsf(y5.x)));
                float qy = d1*ey / (1e-6f + 1e-3f*fmaxf(fabsf(y.y), fabsf(y5.y)));
                *(float2*)(red + e2i) = make_float2(qx*qx, qy*qy);
            }
            __syncthreads();
            if (wid < 8) {
                int r = wid;
                const float* rp = red + ((r>>2)<<10) + (r&3);
                float s = 0.f;
#pragma unroll
                for (int c = 0; c < 8; c++) s += rp[(lane + 32*c)*4];
                s += __shfl_xor_sync(0xffffffffu, s, 16);
                s += __shfl_xor_sync(0xffffffffu, s, 8);
                s += __shfl_xor_sync(0xffffffffu, s, 4);
                s += __shfl_xor_sync(0xffffffffu, s, 2);
                s += __shfl_xor_sync(0xffffffffu, s, 1);
                if (lane == 0) {
                    float en = sqrtf(s * (1.f/256.f));
                    int active = act_s[r];
                    int acc = (en <= 1.f) && active;
                    accfl[r] = acc;
                    float dtc = d_s[r];
                    if (acc) t_s[r] += dtc;
                    if (active) {
                        float fac = 0.9f * powf(en + 1e-10f, -0.2f);
                        fac = fminf(fmaxf(fac, 0.2f), 10.f);
                        dt_s[r] = fmaxf(dtc, 1e-8f) * fac;
                    }
                }
            }
            __syncthreads();
            {
                float2 y = *(float2*)(yT + e2i);
                float2 y5 = *(float2*)(y5T + e2i);
                if (accfl[re0])     y.x = y5.x;
                if (accfl[re0 + 1]) y.y = y5.y;
                *(float2*)(yT + e2i) = y;
            }
            __syncthreads();
            fsal = 1;   // tmpT holds k7 = f(y5); accfl selects per row
#undef COMB2
        }
    }

    // ---------------- Phase D: linear head ----------------
    {
        float fcw = __ldg(fcW + ((e2i & 1023) >> 2));
        float2 y = *(float2*)(yT + e2i);
        *(float2*)(red + e2i) = make_float2(y.x*fcw, y.y*fcw);
        __syncthreads();
        if (wid < 8) {
            int r = wid;
            const float* rp = red + ((r>>2)<<10) + (r&3);
            float s = 0.f;
#pragma unroll
            for (int c = 0; c < 8; c++) s += rp[(lane + 32*c)*4];
            s += __shfl_xor_sync(0xffffffffu, s, 16);
            s += __shfl_xor_sync(0xffffffffu, s, 8);
            s += __shfl_xor_sync(0xffffffffu, s, 4);
            s += __shfl_xor_sync(0xffffffffu, s, 2);
            s += __shfl_xor_sync(0xffffffffu, s, 1);
            if (lane == 0) {
                s += fcb[0];
#pragma unroll
                for (int c = 0; c < 4; c++) s += meta_s[r*4 + c] * fcW[256 + c];
                out[r0 + r] = s;
            }
        }
    }
}

extern "C" void kernel_launch(void* const* d_in, const int* in_sizes, int n_in,
                              void* d_out, int out_size)
{
    const float* x     = (const float*)d_in[0];
    const float* meta  = (const float*)d_in[1];
    const float* eps   = (const float*)d_in[2];
    const float* times = (const float*)d_in[3];
    const float* doses = (const float*)d_in[4];
    const float* gWih  = (const float*)d_in[5];
    const float* gWhh  = (const float*)d_in[6];
    const float* gbih  = (const float*)d_in[7];
    const float* gbhh  = (const float*)d_in[8];
    const float* eW1   = (const float*)d_in[9];
    const float* eb1   = (const float*)d_in[10];
    const float* eW2   = (const float*)d_in[11];
    const float* eb2   = (const float*)d_in[12];
    const float* oW1   = (const float*)d_in[13];
    const float* ob1   = (const float*)d_in[14];
    const float* oW2   = (const float*)d_in[15];
    const float* ob2   = (const float*)d_in[16];
    const float* oW3   = (const float*)d_in[17];
    const float* ob3   = (const float*)d_in[18];
    const float* oW4   = (const float*)d_in[19];
    const float* ob4   = (const float*)d_in[20];
    const float* fcW   = (const float*)d_in[21];
    const float* fcb   = (const float*)d_in[22];
    float* out = (float*)d_out;

    prep_kernel<<<256, 256>>>(gWih, gWhh, eW1, eW2, oW1, oW2, oW3, oW4);

    const int smem_bytes = (11*2048 + 8*2048) * sizeof(float);   // 155648
    static int attr_done = 0;
    if (!attr_done) {
        cudaFuncSetAttribute(node_kernel, cudaFuncAttributeMaxDynamicSharedMemorySize, smem_bytes);
        attr_done = 1;
    }
    node_kernel<<<128, NTH, smem_bytes>>>(x, meta, eps, times, doses,
                                          gbih, gbhh, eb1, eb2,
                                          ob1, ob2, ob3, ob4, fcW, fcb, out);
}

// round 11
// speedup vs baseline: 1.8470x; 1.1082x over previous
#include <cuda_runtime.h>
#include <cuda_fp16.h>
#include <math.h>

#define NTH 512
#define RPB 8

typedef unsigned long long ull;

// ---------------- packed weight scratch (device globals) ----
__device__ float  g_WrzT[2*256*256];   // float2 [i*256+o] = (Wr[o][i], Wz[o][i])
__device__ float  g_WnT [256*256];     // [i*256+o]
__device__ float  g_WihT[8*768];       // [ii*768+o]
__device__ float  g_e1P [256*256];     // "P" packing
__device__ float  g_e2mP[256*256];
__device__ float  g_e2sP[256*256];
__device__ __half g_oWH [4][256*256];  // ODE weights fp16, "P" packing

__global__ void prep_kernel(const float* __restrict__ Wih, const float* __restrict__ Whh,
                            const float* __restrict__ eW1, const float* __restrict__ eW2,
                            const float* __restrict__ oW1, const float* __restrict__ oW2,
                            const float* __restrict__ oW3, const float* __restrict__ oW4)
{
    int idx = blockIdx.x*blockDim.x + threadIdx.x;
    if (idx >= 65536) return;
    int o = idx >> 8, i = idx & 255;
    ((float2*)g_WrzT)[i*256 + o] = make_float2(Whh[o*256 + i], Whh[(o+256)*256 + i]);
    g_WnT[i*256 + o] = Whh[(o+512)*256 + i];
    int pd = i*256 + ((o < 128) ? (2*o) : (2*(o-128) + 1));
    g_e1P [pd] = eW1[o*256 + i];
    g_e2mP[pd] = eW2[o*256 + i];
    g_e2sP[pd] = eW2[(o+256)*256 + i];
    g_oWH[0][pd] = __float2half_rn(oW1[o*256 + i]);
    g_oWH[1][pd] = __float2half_rn(oW2[o*256 + i]);
    g_oWH[2][pd] = __float2half_rn(oW3[o*256 + i]);
    g_oWH[3][pd] = __float2half_rn(oW4[o*256 + i]);
    if (idx < 6144) { int oo = idx / 8, ii = idx % 8; g_WihT[ii*768 + oo] = Wih[idx]; }
}

// ---------------- f32x2 helpers ----------------
__device__ __forceinline__ ull pack2(float a, float b){
    ull r; asm("mov.b64 %0, {%1, %2};" : "=l"(r) : "f"(a), "f"(b)); return r;
}
__device__ __forceinline__ void unpack2(ull v, float& a, float& b){
    asm("mov.b64 {%0, %1}, %2;" : "=f"(a), "=f"(b) : "l"(v));
}
__device__ __forceinline__ void fma2(ull& acc, ull a, ull b){
    asm("fma.rn.f32x2 %0, %1, %2, %0;" : "+l"(acc) : "l"(a), "l"(b));
}

__device__ __forceinline__ float selu_f(float x){
    const float sc = 1.0507009873554805f;
    const float la = 1.7580993408473766f;   // lambda*alpha
    return x > 0.f ? sc*x : fmaf(la, __expf(x), -la);
}
__device__ __forceinline__ float sigmoid_f(float x){
    return 1.f/(1.f + __expf(-x));
}

// dopri5 coefficients
#define A21f 0.2f
#define A31f ((float)(3.0/40.0))
#define A32f ((float)(9.0/40.0))
#define A41f ((float)(44.0/45.0))
#define A42f ((float)(-56.0/15.0))
#define A43f ((float)(32.0/9.0))
#define A51f ((float)(19372.0/6561.0))
#define A52f ((float)(-25360.0/2187.0))
#define A53f ((float)(64448.0/6561.0))
#define A54f ((float)(-212.0/729.0))
#define A61f ((float)(9017.0/3168.0))
#define A62f ((float)(-355.0/33.0))
#define A63f ((float)(46732.0/5247.0))
#define A64f ((float)(49.0/176.0))
#define A65f ((float)(-5103.0/18656.0))
#define BC0f ((float)(35.0/384.0))
#define BC2f ((float)(500.0/1113.0))
#define BC3f ((float)(125.0/192.0))
#define BC4f ((float)(-2187.0/6784.0))
#define BC5f ((float)(11.0/84.0))
#define EC0f ((float)(35.0/384.0 - 5179.0/57600.0))
#define EC2f ((float)(500.0/1113.0 - 7571.0/16695.0))
#define EC3f ((float)(125.0/192.0 - 393.0/640.0))
#define EC4f ((float)(-2187.0/6784.0 + 92097.0/339200.0))
#define EC5f ((float)(11.0/84.0 - 187.0/2100.0))
#define EC6f ((float)(-1.0/40.0))

// SMEM plan (floats): yT=0, tmpT=2048, aT=4096, bT=6144, y5T=8192,
// k1..k6 = 5*2048..10*2048, Pp = 11*2048 (4 chunks of 2048)
#define O_Y   0
#define O_TMP 2048
#define O_A   4096
#define O_B   6144
#define O_Y5  8192
#define O_K1  (5*2048)
#define O_K2  (6*2048)
#define O_K3  (7*2048)
#define O_K4  (8*2048)
#define O_K5  (9*2048)
#define O_K6  (10*2048)
#define O_PP  (11*2048)

// Activation layout (8 rows x 256 cols, 2048 floats):
//   elem (r, c) at buf[(r>>2)*1024 + c*4 + (r&3)]
// Split-K=4 matvec: thread (oc in [0,128), q in [0,4)) owns cols {oc, oc+128},
// all 8 rows, i in [q*64, q*64+64). 512 threads. Combine: thread owns float4 at tid*4.

// main accumulation phase, fp16 weights; returns combine value (pre-activation)
__device__ __forceinline__ float4 mv4h_main(const __half* __restrict__ WT,
                                            const float* __restrict__ bias,
                                            const float* __restrict__ inT,
                                            float* __restrict__ Pp,
                                            int oc, int q, int tid)
{
    const float4* in4 = (const float4*)inT;
    const __half2* w2p = (const __half2*)WT + q*64*128 + oc;
    ull a00=0,a01=0,a02=0,a03=0;
    ull a10=0,a11=0,a12=0,a13=0;
#pragma unroll 16
    for (int ii = 0; ii < 64; ii++) {
        int i = q*64 + ii;
        float2 w = __half22float2(__ldg(w2p + ii*128));
        float4 u0 = in4[i];
        float4 u1 = in4[256 + i];
        ull p0 = pack2(u0.x,u0.y), p1 = pack2(u0.z,u0.w);
        ull p2 = pack2(u1.x,u1.y), p3 = pack2(u1.z,u1.w);
        ull wx = pack2(w.x,w.x), wy = pack2(w.y,w.y);
        fma2(a00,p0,wx); fma2(a01,p1,wx); fma2(a02,p2,wx); fma2(a03,p3,wx);
        fma2(a10,p0,wy); fma2(a11,p1,wy); fma2(a12,p2,wy); fma2(a13,p3,wy);
    }
    float* P = Pp + q*2048;
    float f0,f1,f2,f3;
    unpack2(a00,f0,f1); unpack2(a01,f2,f3); *(float4*)(P + oc*4)        = make_float4(f0,f1,f2,f3);
    unpack2(a10,f0,f1); unpack2(a11,f2,f3); *(float4*)(P + 512 + oc*4)  = make_float4(f0,f1,f2,f3);
    unpack2(a02,f0,f1); unpack2(a03,f2,f3); *(float4*)(P + 1024 + oc*4) = make_float4(f0,f1,f2,f3);
    unpack2(a12,f0,f1); unpack2(a13,f2,f3); *(float4*)(P + 1536 + oc*4) = make_float4(f0,f1,f2,f3);
    __syncthreads();
    const int e4 = tid*4;
    float4 s0 = *(float4*)(Pp + e4);
    float4 s1 = *(float4*)(Pp + 2048 + e4);
    float4 s2 = *(float4*)(Pp + 4096 + e4);
    float4 s3 = *(float4*)(Pp + 6144 + e4);
    float b = __ldg(bias + (tid & 255));
    return make_float4(s0.x+s1.x+s2.x+s3.x+b, s0.y+s1.y+s2.y+s3.y+b,
                       s0.z+s1.z+s2.z+s3.z+b, s0.w+s1.w+s2.w+s3.w+b);
}

// plain layer (selu) -> outT
__device__ __noinline__ void mv4h_selu(const __half* __restrict__ WT,
                                       const float* __restrict__ bias,
                                       const float* __restrict__ inT,
                                       float* __restrict__ outT,
                                       float* __restrict__ Pp,
                                       int oc, int q, int tid)
{
    float4 v = mv4h_main(WT, bias, inT, Pp, oc, q, tid);
    v.x = selu_f(v.x); v.y = selu_f(v.y); v.z = selu_f(v.z); v.w = selu_f(v.w);
    *(float4*)(outT + tid*4) = v;
    __syncthreads();
}

// final ODE layer with fused stage epilogue. epi in [1,7].
__device__ __noinline__ void mv4h_last(const __half* __restrict__ WT,
                                       const float* __restrict__ bias,
                                       const float* __restrict__ inT,
                                       float* __restrict__ outT,
                                       float* __restrict__ sm,
                                       int oc, int q, int tid, int epi, float4 dv)
{
    float* Pp = sm + O_PP;
    float4 v = mv4h_main(WT, bias, inT, Pp, oc, q, tid);
    const int e4 = tid*4;
    *(float4*)(outT + e4) = v;
    float4 y = *(float4*)(sm + O_Y + e4);
#define PER4(DST, EX) do { float4 _o; _o.x=EX(x); _o.y=EX(y); _o.z=EX(z); _o.w=EX(w); \
                           *(float4*)(DST + e4) = _o; } while(0)
    if (epi == 1) {
#define S1(c) fmaf(dv.c, A21f*v.c, y.c)
        PER4(sm + O_TMP, S1);
#undef S1
    } else if (epi == 2) {
        float4 k1 = *(float4*)(sm + O_K1 + e4);
#define S2(c) fmaf(dv.c, A31f*k1.c + A32f*v.c, y.c)
        PER4(sm + O_TMP, S2);
#undef S2
    } else if (epi == 3) {
        float4 k1 = *(float4*)(sm + O_K1 + e4);
        float4 k2 = *(float4*)(sm + O_K2 + e4);
#define S3(c) fmaf(dv.c, A41f*k1.c + A42f*k2.c + A43f*v.c, y.c)
        PER4(sm + O_TMP, S3);
#undef S3
    } else if (epi == 4) {
        float4 k1 = *(float4*)(sm + O_K1 + e4);
        float4 k2 = *(float4*)(sm + O_K2 + e4);
        float4 k3 = *(float4*)(sm + O_K3 + e4);
#define S4(c) fmaf(dv.c, A51f*k1.c + A52f*k2.c + A53f*k3.c + A54f*v.c, y.c)
        PER4(sm + O_TMP, S4);
#undef S4
    } else if (epi == 5) {
        float4 k1 = *(float4*)(sm + O_K1 + e4);
        float4 k2 = *(float4*)(sm + O_K2 + e4);
        float4 k3 = *(float4*)(sm + O_K3 + e4);
        float4 k4 = *(float4*)(sm + O_K4 + e4);
#define S5(c) fmaf(dv.c, A61f*k1.c + A62f*k2.c + A63f*k3.c + A64f*k4.c + A65f*v.c, y.c)
        PER4(sm + O_TMP, S5);
#undef S5
    } else if (epi == 6) {
        float4 k1 = *(float4*)(sm + O_K1 + e4);
        float4 k3 = *(float4*)(sm + O_K3 + e4);
        float4 k4 = *(float4*)(sm + O_K4 + e4);
        float4 k5 = *(float4*)(sm + O_K5 + e4);
#define S6(c) fmaf(dv.c, BC0f*k1.c + BC2f*k3.c + BC3f*k4.c + BC4f*k5.c + BC5f*v.c, y.c)
        PER4(sm + O_Y5, S6);
#undef S6
    } else {   // epi == 7: error contributions -> red (== aT)
        float4 k1 = *(float4*)(sm + O_K1 + e4);
        float4 k3 = *(float4*)(sm + O_K3 + e4);
        float4 k4 = *(float4*)(sm + O_K4 + e4);
        float4 k5 = *(float4*)(sm + O_K5 + e4);
        float4 k6 = *(float4*)(sm + O_K6 + e4);
        float4 y5 = *(float4*)(sm + O_Y5 + e4);
#define S7(c) ({ float _e = EC0f*k1.c + EC2f*k3.c + EC3f*k4.c + EC4f*k5.c + EC5f*k6.c + EC6f*v.c; \
                 float _q = dv.c*_e / (1e-6f + 1e-3f*fmaxf(fabsf(y.c), fabsf(y5.c))); _q*_q; })
        PER4(sm + O_A, S7);
#undef S7
    }
#undef PER4
    __syncthreads();
}

__device__ __noinline__ void feval_fused(float* __restrict__ sm,
                                         const float* __restrict__ inT,
                                         float* __restrict__ outT,
                                         const float* ob1, const float* ob2,
                                         const float* ob3, const float* ob4,
                                         int oc, int q, int tid, int epi, float4 dv)
{
    float* Pp = sm + O_PP;
    mv4h_selu(g_oWH[0], ob1, inT, sm + O_A, Pp, oc, q, tid);
    mv4h_selu(g_oWH[1], ob2, sm + O_A, sm + O_B, Pp, oc, q, tid);
    mv4h_selu(g_oWH[2], ob3, sm + O_B, sm + O_A, Pp, oc, q, tid);
    mv4h_last(g_oWH[3], ob4, sm + O_A, outT, sm, oc, q, tid, epi, dv);
}

// fp32-weight matvec (encoder), act: 0 none, 2 relu
__device__ __noinline__ void mv4f(const float* __restrict__ WT,
                                  const float* __restrict__ bias,
                                  const float* __restrict__ inT,
                                  float* __restrict__ outT,
                                  float* __restrict__ Pp,
                                  int oc, int q, int tid, int act)
{
    const float4* in4 = (const float4*)inT;
    const float2* w2p = (const float2*)WT + q*64*128 + oc;
    ull a00=0,a01=0,a02=0,a03=0;
    ull a10=0,a11=0,a12=0,a13=0;
#pragma unroll 8
    for (int ii = 0; ii < 64; ii++) {
        int i = q*64 + ii;
        float2 w = __ldg(w2p + ii*128);
        float4 u0 = in4[i];
        float4 u1 = in4[256 + i];
        ull p0 = pack2(u0.x,u0.y), p1 = pack2(u0.z,u0.w);
        ull p2 = pack2(u1.x,u1.y), p3 = pack2(u1.z,u1.w);
        ull wx = pack2(w.x,w.x), wy = pack2(w.y,w.y);
        fma2(a00,p0,wx); fma2(a01,p1,wx); fma2(a02,p2,wx); fma2(a03,p3,wx);
        fma2(a10,p0,wy); fma2(a11,p1,wy); fma2(a12,p2,wy); fma2(a13,p3,wy);
    }
    float* P = Pp + q*2048;
    float f0,f1,f2,f3;
    unpack2(a00,f0,f1); unpack2(a01,f2,f3); *(float4*)(P + oc*4)        = make_float4(f0,f1,f2,f3);
    unpack2(a10,f0,f1); unpack2(a11,f2,f3); *(float4*)(P + 512 + oc*4)  = make_float4(f0,f1,f2,f3);
    unpack2(a02,f0,f1); unpack2(a03,f2,f3); *(float4*)(P + 1024 + oc*4) = make_float4(f0,f1,f2,f3);
    unpack2(a12,f0,f1); unpack2(a13,f2,f3); *(float4*)(P + 1536 + oc*4) = make_float4(f0,f1,f2,f3);
    __syncthreads();
    const int e4 = tid*4;
    float4 s0 = *(float4*)(Pp + e4);
    float4 s1 = *(float4*)(Pp + 2048 + e4);
    float4 s2 = *(float4*)(Pp + 4096 + e4);
    float4 s3 = *(float4*)(Pp + 6144 + e4);
    float b = __ldg(bias + (tid & 255));
    float4 v = make_float4(s0.x+s1.x+s2.x+s3.x+b, s0.y+s1.y+s2.y+s3.y+b,
                           s0.z+s1.z+s2.z+s3.z+b, s0.w+s1.w+s2.w+s3.w+b);
    if (act == 2) { v.x=fmaxf(v.x,0.f); v.y=fmaxf(v.y,0.f); v.z=fmaxf(v.z,0.f); v.w=fmaxf(v.w,0.f); }
    *(float4*)(outT + e4) = v;
    __syncthreads();
}

// ---------------- main persistent kernel ----------------
__global__ __launch_bounds__(NTH, 1)
void node_kernel(const float* __restrict__ x,     const float* __restrict__ meta,
                 const float* __restrict__ eps,   const float* __restrict__ times,
                 const float* __restrict__ doses,
                 const float* __restrict__ gbih,  const float* __restrict__ gbhh,
                 const float* __restrict__ eb1,   const float* __restrict__ eb2,
                 const float* __restrict__ ob1,   const float* __restrict__ ob2,
                 const float* __restrict__ ob3,   const float* __restrict__ ob4,
                 const float* __restrict__ fcW,   const float* __restrict__ fcb,
                 float* __restrict__ out)
{
    extern __shared__ float sm[];
    float* yT   = sm + O_Y;
    float* tmpT = sm + O_TMP;
    float* red  = sm + O_A;      // aT doubles as error buffer
    float* y5T  = sm + O_Y5;
    float* k1T  = sm + O_K1;     // x cache during GRU
    float* Pp   = sm + O_PP;     // split-K partials / GRU gate planes
    float* xc   = k1T;

    __shared__ float t_s[8], t1_s[8], dt_s[8], d_s[8], ds_s[8], meta_s[32];
    __shared__ int   act_s[8], accfl[8];

    const int tid  = threadIdx.x;
    const int oc   = tid & 127;      // ODE: column pair {oc, oc+128}
    const int q    = tid >> 7;       // ODE: K-chunk 0..3
    const int o    = tid & 255;      // GRU: column
    const int qg   = tid >> 8;       // GRU: 0 -> r,z ; 1 -> n
    const int wid  = tid >> 5;
    const int lane = tid & 31;
    const int r0   = blockIdx.x * RPB;
    const int e4   = tid*4;          // my float4 in [0,2048)
    const int hh   = tid >> 8;       // my row block: rows 4hh..4hh+3
    const int rb   = hh*4;

    for (int e = tid; e < 2048; e += NTH) { xc[e] = x[r0*256 + e]; yT[e] = 0.f; }
    if (tid < 32) meta_s[tid] = meta[r0*4 + tid];

    // GRU register weights / biases
    float wA[8], wB[8];
    float bA, bB, bN = 0.f;
    if (qg == 0) {
#pragma unroll
        for (int c = 0; c < 8; c++) { wA[c] = g_WihT[c*768 + o]; wB[c] = g_WihT[c*768 + o + 256]; }
        bA = gbih[o] + gbhh[o];
        bB = gbih[o+256] + gbhh[o+256];
    } else {
#pragma unroll
        for (int c = 0; c < 8; c++) { wA[c] = g_WihT[c*768 + o + 512]; wB[c] = 0.f; }
        bA = gbhh[o + 512];
        bN = gbih[o + 512];
        bB = 0.f;
    }
    __syncthreads();

    // ---------------- Phase A: GRU over 64 timesteps ----------------
    for (int t = 0; t < 64; t++) {
        if (qg == 0) {
            // gates r,z over all 8 rows
            ull ar0 = pack2(bA,bA), ar1 = ar0, ar2 = ar0, ar3 = ar0;
            ull az0 = pack2(bB,bB), az1 = az0, az2 = az0, az3 = az0;
            const float2* wrz = (const float2*)g_WrzT + o;
            const float4* h4 = (const float4*)yT;
#pragma unroll 8
            for (int i = 0; i < 256; i++) {
                float2 w = __ldg(wrz + i*256);
                float4 u0 = h4[i];
                float4 u1 = h4[256 + i];
                ull p0 = pack2(u0.x,u0.y), p1 = pack2(u0.z,u0.w);
                ull p2 = pack2(u1.x,u1.y), p3 = pack2(u1.z,u1.w);
                ull wx = pack2(w.x,w.x), wy = pack2(w.y,w.y);
                fma2(ar0,p0,wx); fma2(ar1,p1,wx); fma2(ar2,p2,wx); fma2(ar3,p3,wx);
                fma2(az0,p0,wy); fma2(az1,p1,wy); fma2(az2,p2,wy); fma2(az3,p3,wy);
            }
            float fr[8], fz[8];
            unpack2(ar0,fr[0],fr[1]); unpack2(ar1,fr[2],fr[3]);
            unpack2(ar2,fr[4],fr[5]); unpack2(ar3,fr[6],fr[7]);
            unpack2(az0,fz[0],fz[1]); unpack2(az1,fz[2],fz[3]);
            unpack2(az2,fz[4],fz[5]); unpack2(az3,fz[6],fz[7]);
#pragma unroll
            for (int r = 0; r < 8; r++) {
                float sr = 0.f, sz = 0.f;
#pragma unroll
                for (int c = 0; c < 4; c++) {
                    float xv = xc[r*256 + t*4 + c];
                    sr = fmaf(xv, wA[c], sr); sz = fmaf(xv, wB[c], sz);
                }
#pragma unroll
                for (int c = 0; c < 4; c++) {
                    float mv = meta_s[r*4 + c];
                    sr = fmaf(mv, wA[4+c], sr); sz = fmaf(mv, wB[4+c], sz);
                }
                fr[r] = sigmoid_f(fr[r] + sr);
                fz[r] = sigmoid_f(fz[r] + sz);
            }
            *(float4*)(Pp + o*4)           = make_float4(fr[0],fr[1],fr[2],fr[3]);
            *(float4*)(Pp + 1024 + o*4)    = make_float4(fr[4],fr[5],fr[6],fr[7]);
            *(float4*)(Pp + 2048 + o*4)    = make_float4(fz[0],fz[1],fz[2],fz[3]);
            *(float4*)(Pp + 3072 + o*4)    = make_float4(fz[4],fz[5],fz[6],fz[7]);
            __syncthreads();
            __syncthreads();
        } else {
            // gate n over all 8 rows
            ull an0 = pack2(bA,bA), an1 = an0, an2 = an0, an3 = an0;
            const float* wn = g_WnT + o;
            const float4* h4 = (const float4*)yT;
#pragma unroll 8
            for (int i = 0; i < 256; i++) {
                float w = __ldg(wn + i*256);
                float4 u0 = h4[i];
                float4 u1 = h4[256 + i];
                ull w2 = pack2(w,w);
                fma2(an0, pack2(u0.x,u0.y), w2);
                fma2(an1, pack2(u0.z,u0.w), w2);
                fma2(an2, pack2(u1.x,u1.y), w2);
                fma2(an3, pack2(u1.z,u1.w), w2);
            }
            float hn[8];
            unpack2(an0,hn[0],hn[1]); unpack2(an1,hn[2],hn[3]);
            unpack2(an2,hn[4],hn[5]); unpack2(an3,hn[6],hn[7]);
            float inn[8];
#pragma unroll
            for (int r = 0; r < 8; r++) {
                float s = bN;
#pragma unroll
                for (int c = 0; c < 4; c++) s = fmaf(xc[r*256 + t*4 + c], wA[c], s);
#pragma unroll
                for (int c = 0; c < 4; c++) s = fmaf(meta_s[r*4 + c], wA[4+c], s);
                inn[r] = s;
            }
            __syncthreads();
            float4 R0 = *(float4*)(Pp + o*4);
            float4 R1 = *(float4*)(Pp + 1024 + o*4);
            float4 Z0 = *(float4*)(Pp + 2048 + o*4);
            float4 Z1 = *(float4*)(Pp + 3072 + o*4);
            float4 h0 = *(float4*)(yT + o*4);
            float4 h1 = *(float4*)(yT + 1024 + o*4);
            float Rr[8] = {R0.x,R0.y,R0.z,R0.w,R1.x,R1.y,R1.z,R1.w};
            float Zr[8] = {Z0.x,Z0.y,Z0.z,Z0.w,Z1.x,Z1.y,Z1.z,Z1.w};
            float hr[8] = {h0.x,h0.y,h0.z,h0.w,h1.x,h1.y,h1.z,h1.w};
            float hnew[8];
#pragma unroll
            for (int r = 0; r < 8; r++) {
                float n = tanhf(inn[r] + Rr[r]*hn[r]);
                hnew[r] = (1.f - Zr[r])*n + Zr[r]*hr[r];
            }
            *(float4*)(yT + o*4)        = make_float4(hnew[0],hnew[1],hnew[2],hnew[3]);
            *(float4*)(yT + 1024 + o*4) = make_float4(hnew[4],hnew[5],hnew[6],hnew[7]);
            __syncthreads();
        }
    }

    // ---------------- Phase B: encoder -> y0 ----------------
    mv4f(g_e1P,  eb1,       yT,          sm + O_B,  Pp, oc, q, tid, 2);  // relu -> bT
    mv4f(g_e2mP, eb2,       sm + O_B,    sm + O_A,  Pp, oc, q, tid, 0);  // mean -> aT
    mv4f(g_e2sP, eb2 + 256, sm + O_B,    y5T,       Pp, oc, q, tid, 0);  // std  -> y5T
    {
        int c = tid & 255;
        float4 m = *(float4*)(sm + O_A + e4);
        float4 s = *(float4*)(y5T + e4);
        float4 y0;
        y0.x = fmaf(__ldg(eps + (r0 + rb + 0)*256 + c), s.x, m.x);
        y0.y = fmaf(__ldg(eps + (r0 + rb + 1)*256 + c), s.y, m.y);
        y0.z = fmaf(__ldg(eps + (r0 + rb + 2)*256 + c), s.z, m.z);
        y0.w = fmaf(__ldg(eps + (r0 + rb + 3)*256 + c), s.w, m.w);
        *(float4*)(yT + e4) = y0;
    }
    __syncthreads();

    // ---------------- Phase C: 4 x dopri5 (FSAL + fused epilogues) --------
    for (int j = 0; j < 4; j++) {
        if (tid < 8) {
            int row = r0 + tid;
            float t0v = times[(j*1024 + row)*2 + 0];
            float t1v = times[(j*1024 + row)*2 + 1];
            t_s[tid]  = t0v;
            t1_s[tid] = t1v;
            dt_s[tid] = fmaxf(t1v - t0v, 1e-6f) * 0.1f;
            ds_s[tid] = (t0v < t1v) ? doses[j*1024 + row] : 0.f;
        }
        __syncthreads();
        {
            float4 y = *(float4*)(yT + e4);
            y.x += ds_s[rb+0]; y.y += ds_s[rb+1]; y.z += ds_s[rb+2]; y.w += ds_s[rb+3];
            *(float4*)(yT + e4) = y;
        }

        int fsal = 0;
        for (int step = 0; step < 32; step++) {
            int myact = 0;
            if (tid < 8) {
                float tt = t_s[tid], t1v = t1_s[tid];
                myact = (tt < t1v) ? 1 : 0;
                act_s[tid] = myact;
                float rem = fmaxf(t1v - tt, 0.f);
                d_s[tid] = fminf(fmaxf(dt_s[tid], 0.f), rem);
            }
            if (!__syncthreads_or(myact)) break;   // uniform exit

            const float4 dv = make_float4(d_s[rb+0], d_s[rb+1], d_s[rb+2], d_s[rb+3]);

            if (fsal) {
                // k1 select (exact FSAL) + stage-1 combine, one block + one sync
                float4 kp  = *(float4*)(k1T + e4);
                float4 k7v = *(float4*)(tmpT + e4);
                if (accfl[rb+0]) kp.x = k7v.x;
                if (accfl[rb+1]) kp.y = k7v.y;
                if (accfl[rb+2]) kp.z = k7v.z;
                if (accfl[rb+3]) kp.w = k7v.w;
                *(float4*)(k1T + e4) = kp;
                float4 y = *(float4*)(yT + e4);
                float4 tt;
                tt.x = fmaf(dv.x, A21f*kp.x, y.x);
                tt.y = fmaf(dv.y, A21f*kp.y, y.y);
                tt.z = fmaf(dv.z, A21f*kp.z, y.z);
                tt.w = fmaf(dv.w, A21f*kp.w, y.w);
                *(float4*)(tmpT + e4) = tt;
                __syncthreads();
            } else {
                feval_fused(sm, yT, k1T, ob1, ob2, ob3, ob4, oc, q, tid, 1, dv);
            }
            feval_fused(sm, tmpT, sm + O_K2, ob1, ob2, ob3, ob4, oc, q, tid, 2, dv);
            feval_fused(sm, tmpT, sm + O_K3, ob1, ob2, ob3, ob4, oc, q, tid, 3, dv);
            feval_fused(sm, tmpT, sm + O_K4, ob1, ob2, ob3, ob4, oc, q, tid, 4, dv);
            feval_fused(sm, tmpT, sm + O_K5, ob1, ob2, ob3, ob4, oc, q, tid, 5, dv);
            feval_fused(sm, tmpT, sm + O_K6, ob1, ob2, ob3, ob4, oc, q, tid, 6, dv);  // -> y5T
            feval_fused(sm, y5T,  tmpT,     ob1, ob2, ob3, ob4, oc, q, tid, 7, dv);  // k7 + err->red

            // control (red valid after mv4h_last trailing sync)
            if (wid < 8) {
                int r = wid;
                const float* rp = red + ((r>>2)<<10) + (r&3);
                float s = 0.f;
#pragma unroll
                for (int c = 0; c < 8; c++) s += rp[(lane + 32*c)*4];
                s += __shfl_xor_sync(0xffffffffu, s, 16);
                s += __shfl_xor_sync(0xffffffffu, s, 8);
                s += __shfl_xor_sync(0xffffffffu, s, 4);
                s += __shfl_xor_sync(0xffffffffu, s, 2);
                s += __shfl_xor_sync(0xffffffffu, s, 1);
                if (lane == 0) {
                    float en = sqrtf(s * (1.f/256.f));
                    int active = act_s[r];
                    int acc = (en <= 1.f) && active;
                    accfl[r] = acc;
                    float dtc = d_s[r];
                    if (acc) t_s[r] += dtc;
                    if (active) {
                        float fac = 0.9f * __expf(-0.2f * __logf(en + 1e-10f));
                        fac = fminf(fmaxf(fac, 0.2f), 10.f);
                        dt_s[r] = fmaxf(dtc, 1e-8f) * fac;
                    }
                }
            }
            __syncthreads();
            {
                float4 y  = *(float4*)(yT + e4);
                float4 y5 = *(float4*)(y5T + e4);
                if (accfl[rb+0]) y.x = y5.x;
                if (accfl[rb+1]) y.y = y5.y;
                if (accfl[rb+2]) y.z = y5.z;
                if (accfl[rb+3]) y.w = y5.w;
                *(float4*)(yT + e4) = y;
            }
            __syncthreads();
            fsal = 1;
        }
    }

    // ---------------- Phase D: linear head ----------------
    {
        float fcw = __ldg(fcW + (tid & 255));
        float4 y = *(float4*)(yT + e4);
        *(float4*)(red + e4) = make_float4(y.x*fcw, y.y*fcw, y.z*fcw, y.w*fcw);
        __syncthreads();
        if (wid < 8) {
            int r = wid;
            const float* rp = red + ((r>>2)<<10) + (r&3);
            float s = 0.f;
#pragma unroll
            for (int c = 0; c < 8; c++) s += rp[(lane + 32*c)*4];
            s += __shfl_xor_sync(0xffffffffu, s, 16);
            s += __shfl_xor_sync(0xffffffffu, s, 8);
            s += __shfl_xor_sync(0xffffffffu, s, 4);
            s += __shfl_xor_sync(0xffffffffu, s, 2);
            s += __shfl_xor_sync(0xffffffffu, s, 1);
            if (lane == 0) {
                s += fcb[0];
#pragma unroll
                for (int c = 0; c < 4; c++) s += meta_s[r*4 + c] * fcW[256 + c];
                out[r0 + r] = s;
            }
        }
    }
}

extern "C" void kernel_launch(void* const* d_in, const int* in_sizes, int n_in,
                              void* d_out, int out_size)
{
    const float* x     = (const float*)d_in[0];
    const float* meta  = (const float*)d_in[1];
    const float* eps   = (const float*)d_in[2];
    const float* times = (const float*)d_in[3];
    const float* doses = (const float*)d_in[4];
    const float* gWih  = (const float*)d_in[5];
    const float* gWhh  = (const float*)d_in[6];
    const float* gbih  = (const float*)d_in[7];
    const float* gbhh  = (const float*)d_in[8];
    const float* eW1   = (const float*)d_in[9];
    const float* eb1   = (const float*)d_in[10];
    const float* eW2   = (const float*)d_in[11];
    const float* eb2   = (const float*)d_in[12];
    const float* oW1   = (const float*)d_in[13];
    const float* ob1   = (const float*)d_in[14];
    const float* oW2   = (const float*)d_in[15];
    const float* ob2   = (const float*)d_in[16];
    const float* oW3   = (const float*)d_in[17];
    const float* ob3   = (const float*)d_in[18];
    const float* oW4   = (const float*)d_in[19];
    const float* ob4   = (const float*)d_in[20];
    const float* fcW   = (const float*)d_in[21];
    const float* fcb   = (const float*)d_in[22];
    float* out = (float*)d_out;

    prep_kernel<<<256, 256>>>(gWih, gWhh, eW1, eW2, oW1, oW2, oW3, oW4);

    const int smem_bytes = (11*2048 + 4*2048) * sizeof(float);   // 122880
    static int attr_done = 0;
    if (!attr_done) {
        cudaFuncSetAttribute(node_kernel, cudaFuncAttributeMaxDynamicSharedMemorySize, smem_bytes);
        attr_done = 1;
    }
    node_kernel<<<128, NTH, smem_bytes>>>(x, meta, eps, times, doses,
                                          gbih, gbhh, eb1, eb2,
                                          ob1, ob2, ob3, ob4, fcW, fcb, out);
}